// round 10
// baseline (speedup 1.0000x reference)
#include <cuda_runtime.h>
#include <mma.h>
#include <math.h>

using namespace nvcuda;

// ---------------- problem constants ----------------
#define BATCH   2
#define SEQ     512
#define NTOK    (BATCH*SEQ)          // 1024
#define DMODEL  1024
#define DINNER  2048
#define DSTATE  64
#define HEADDIM 64
#define NHEADS  32
#define CONVDIM (DINNER + 2*DSTATE)  // 2176
#define EPROJ   (2*DINNER + 2*DSTATE + NHEADS) // 4256
#define DCONV   4
#define VNUM    3
#define HORIZON 20
#define RMS_EPS 1e-5f
#define CHUNK   64
#define NCHUNK  (SEQ/CHUNK)          // 8

// ---------------- device scratch (no cudaMalloc allowed) ----------------
__device__ float g_zx    [NTOK * EPROJ];    // in_proj output
__device__ float g_xc    [NTOK * CONVDIM];  // conv+silu output
__device__ float g_dt    [NTOK * NHEADS];   // softplus(dt)
__device__ float g_la    [NTOK * NHEADS];   // dt * A  (log of dA)
__device__ float g_dA    [NTOK * NHEADS];   // exp(dt*A)
__device__ float g_acum  [NTOK * NHEADS];   // within-chunk cumprod of dA
__device__ float g_state [BATCH*NHEADS*NCHUNK*HEADDIM*DSTATE]; // chunk-local end states
__device__ float g_hstart[BATCH*NHEADS*NCHUNK*HEADDIM*DSTATE]; // state at chunk start
__device__ float g_y     [NTOK * DINNER];   // scan output + D*x
__device__ float g_nrm   [NTOK * DINNER];   // gated + rmsnormed
__device__ float g_h     [NTOK * DMODEL];   // out_proj output

__device__ __forceinline__ float siluf(float x) { return x / (1.0f + expf(-x)); }
__device__ __forceinline__ float softplusf(float x) {
    return (x > 20.0f) ? x : log1pf(expf(x));
}

// ---------------- cp.async helpers ----------------
__device__ __forceinline__ void cp_async16(void* smem, const void* gmem) {
    unsigned saddr = (unsigned)__cvta_generic_to_shared(smem);
    asm volatile("cp.async.cg.shared.global [%0], [%1], 16;\n" :: "r"(saddr), "l"(gmem));
}
__device__ __forceinline__ void cp_commit() {
    asm volatile("cp.async.commit_group;\n");
}
template <int N>
__device__ __forceinline__ void cp_wait() {
    asm volatile("cp.async.wait_group %0;\n" :: "n"(N));
}

// ---------------- tf32 tensor-core GEMM NT (3-stage cp.async ring) --------
// C[M,N] = A[M,K] * B[N,K]^T. A row-major MxK, B row-major NxK.
// BM=128, BN=64, BK=32; 256 threads = 8 warps (4 m x 2 n), warp tile 32x32.
#define TBM 128
#define TBN 64
#define TBK 32
#define TLD (TBK + 8)                    // 40 floats row stride
#define STAGES 3
#define AS_STRIDE (TBM*TLD)              // 5120 floats / stage
#define BS_STRIDE (TBN*TLD)              // 2560 floats / stage
#define GEMM_SMEM_BYTES (STAGES*(AS_STRIDE+BS_STRIDE)*4)   // 92160 B

__global__ void __launch_bounds__(256)
gemm_tf32(const float* __restrict__ A, const float* __restrict__ B,
          float* __restrict__ C, int M, int N, int K)
{
    extern __shared__ __align__(16) float smem[];
    float* As = smem;                         // [STAGES][TBM][TLD]
    float* Bs = smem + STAGES * AS_STRIDE;    // [STAGES][TBN][TLD]

    const int tid  = threadIdx.x;
    const int warp = tid >> 5;
    const int wm   = (warp & 3) * 32;    // 4 warps over M
    const int wn   = (warp >> 2) * 32;   // 2 warps over N
    const int m0   = blockIdx.y * TBM;
    const int n0   = blockIdx.x * TBN;

    wmma::fragment<wmma::accumulator, 16, 16, 8, float> acc[2][2];
#pragma unroll
    for (int i = 0; i < 2; i++)
#pragma unroll
        for (int j = 0; j < 2; j++) wmma::fill_fragment(acc[i][j], 0.0f);

    const int ntiles = K / TBK;

    // --- async copy of K-tile kt into ring stage stg ---
    auto issue_tile = [&](int kt, int stg) {
        const size_t ko = (size_t)kt * TBK;
        float* as = As + stg * AS_STRIDE;
        float* bs = Bs + stg * BS_STRIDE;
#pragma unroll
        for (int k = 0; k < 4; k++) {            // 1024 float4 slots for A
            int slot = tid + k * 256;
            int r = slot >> 3, c = (slot & 7) * 4;
            cp_async16(&as[r * TLD + c], A + (size_t)(m0 + r) * K + ko + c);
        }
#pragma unroll
        for (int k = 0; k < 2; k++) {            // 512 float4 slots for B
            int slot = tid + k * 256;
            int r = slot >> 3, c = (slot & 7) * 4;
            int rr = (n0 + r < N) ? (n0 + r) : (N - 1);   // clamp; masked at store
            cp_async16(&bs[r * TLD + c], B + (size_t)rr * K + ko + c);
        }
        cp_commit();
    };

    // prologue: stages 0..STAGES-2 in flight
    issue_tile(0, 0);
    if (ntiles > 1) issue_tile(1, 1);

    for (int kt = 0; kt < ntiles; kt++) {
        if (kt + 1 == ntiles) cp_wait<0>(); else cp_wait<1>();
        __syncthreads();                   // tile kt resident; kt-1 compute done
        if (kt + STAGES - 1 < ntiles)
            issue_tile(kt + STAGES - 1, (kt + STAGES - 1) % STAGES);

        const float* Asb = As + (kt % STAGES) * AS_STRIDE;
        const float* Bsb = Bs + (kt % STAGES) * BS_STRIDE;
#pragma unroll
        for (int ks = 0; ks < TBK / 8; ks++) {
            wmma::fragment<wmma::matrix_a, 16, 16, 8, wmma::precision::tf32, wmma::row_major> af[2];
            wmma::fragment<wmma::matrix_b, 16, 16, 8, wmma::precision::tf32, wmma::col_major> bf[2];
#pragma unroll
            for (int i = 0; i < 2; i++) {
                wmma::load_matrix_sync(af[i], Asb + (wm + i * 16) * TLD + ks * 8, TLD);
#pragma unroll
                for (int e = 0; e < af[i].num_elements; e++)
                    af[i].x[e] = wmma::__float_to_tf32(af[i].x[e]);
            }
#pragma unroll
            for (int j = 0; j < 2; j++) {
                wmma::load_matrix_sync(bf[j], Bsb + (wn + j * 16) * TLD + ks * 8, TLD);
#pragma unroll
                for (int e = 0; e < bf[j].num_elements; e++)
                    bf[j].x[e] = wmma::__float_to_tf32(bf[j].x[e]);
            }
#pragma unroll
            for (int i = 0; i < 2; i++)
#pragma unroll
                for (int j = 0; j < 2; j++)
                    wmma::mma_sync(acc[i][j], af[i], bf[j], acc[i][j]);
        }
    }

#pragma unroll
    for (int i = 0; i < 2; i++)
#pragma unroll
        for (int j = 0; j < 2; j++) {
            int n = n0 + wn + j * 16;
            if (n < N)   // N % 16 == 0 -> tiles are all-or-nothing
                wmma::store_matrix_sync(&C[(size_t)(m0 + wm + i * 16) * N + n],
                                        acc[i][j], N, wmma::mem_row_major);
        }
}

// ---------------- conv (depthwise causal, width 4) + silu ----------------
__global__ void __launch_bounds__(256)
conv_silu_kernel(const float* __restrict__ conv_w, const float* __restrict__ conv_b)
{
    int idx = blockIdx.x * blockDim.x + threadIdx.x;
    if (idx >= NTOK * CONVDIM) return;
    int c = idx % CONVDIM;
    int t = idx / CONVDIM;
    int s = t & (SEQ - 1);
    int b = t >> 9;

    float acc = conv_b[c];
#pragma unroll
    for (int k = 0; k < DCONV; k++) {
        int ss = s + k - (DCONV - 1);
        if (ss >= 0)
            acc = fmaf(conv_w[c * DCONV + k],
                       g_zx[(size_t)(b * SEQ + ss) * EPROJ + DINNER + c], acc);
    }
    g_xc[(size_t)t * CONVDIM + c] = siluf(acc);
}

// ---------------- dt = softplus(dt_raw + bias), la = dt*A, dA = exp(la) ----
__global__ void __launch_bounds__(256)
dt_kernel(const float* __restrict__ dt_bias, const float* __restrict__ A_log)
{
    int idx = blockIdx.x * blockDim.x + threadIdx.x;
    if (idx >= NTOK * NHEADS) return;
    int hh = idx & (NHEADS - 1);
    int t  = idx >> 5;
    float raw = g_zx[(size_t)t * EPROJ + DINNER + CONVDIM + hh];
    float dtv = softplusf(raw + dt_bias[hh]);
    float Ah  = -expf(A_log[hh]);
    float la  = dtv * Ah;
    g_dt[idx] = dtv;
    g_la[idx] = la;
    g_dA[idx] = expf(la);
}

// ---------------- within-chunk cumulative dA via warp log-scan ------------
__global__ void __launch_bounds__(256)
acum_kernel()
{
    int w    = (blockIdx.x * 256 + threadIdx.x) >> 5;   // 0..511
    int lane = threadIdx.x & 31;
    if (w >= BATCH * NHEADS * NCHUNK) return;
    int chunk = w & (NCHUNK - 1);
    int hh    = (w >> 3) & (NHEADS - 1);
    int b     = w >> 8;
    int base  = (b * SEQ + chunk * CHUNK) * NHEADS + hh;

    float l0 = g_la[base + (lane * 2)     * NHEADS];
    float l1 = g_la[base + (lane * 2 + 1) * NHEADS];
    float loc = l0 + l1;
    float sc = loc;
#pragma unroll
    for (int off = 1; off < 32; off <<= 1) {
        float v = __shfl_up_sync(0xffffffffu, sc, off);
        if (lane >= off) sc += v;
    }
    float excl = sc - loc;
    g_acum[base + (lane * 2)     * NHEADS] = expf(excl + l0);
    g_acum[base + (lane * 2 + 1) * NHEADS] = expf(excl + loc);
}

// ---------------- pass 1: intra-chunk scan (zero initial state) ----------------
__global__ void __launch_bounds__(128)
scan_chunk_kernel(const float* __restrict__ Dp)
{
    const int bz = blockIdx.z;
    const int b  = bz >> 5;
    const int hh = bz & (NHEADS - 1);
    const int chunk = blockIdx.y;
    const int pb = blockIdx.x * 16;
    const int t  = threadIdx.x;
    const int lp = t >> 3;
    const int n0 = (t & 7) * 8;

    __shared__ __align__(16) float sB[32][64];
    __shared__ __align__(16) float sC[32][64];
    __shared__ __align__(16) float sX[32][16];
    __shared__ float sdA[32], sdt[32];

    float hst[8];
#pragma unroll
    for (int j = 0; j < 8; j++) hst[j] = 0.0f;

    const float Dh = Dp[hh];
    const size_t rowbase = (size_t)(b * SEQ) * CONVDIM;

#pragma unroll
    for (int sub = 0; sub < 2; sub++) {
        const int s0 = chunk * CHUNK + sub * 32;
        for (int i = t; i < 512; i += 128) {
            int si = i >> 4, j4 = (i & 15) * 4;
            size_t r = rowbase + (size_t)(s0 + si) * CONVDIM;
            *(float4*)&sB[si][j4] = *(const float4*)&g_xc[r + DINNER + j4];
            *(float4*)&sC[si][j4] = *(const float4*)&g_xc[r + DINNER + DSTATE + j4];
        }
        {
            int si = t >> 2, j4 = (t & 3) * 4;
            size_t r = rowbase + (size_t)(s0 + si) * CONVDIM;
            *(float4*)&sX[si][j4] = *(const float4*)&g_xc[r + hh * HEADDIM + pb + j4];
        }
        if (t < 32) {
            int idx = (b * SEQ + s0 + t) * NHEADS + hh;
            sdA[t] = g_dA[idx];
            sdt[t] = g_dt[idx];
        }
        __syncthreads();

        for (int si = 0; si < 32; si++) {
            float dAv = sdA[si];
            float xv  = sX[si][lp];
            float dtx = sdt[si] * xv;
            float4 b0 = *(const float4*)&sB[si][n0];
            float4 b1 = *(const float4*)&sB[si][n0 + 4];
            float4 c0 = *(const float4*)&sC[si][n0];
            float4 c1 = *(const float4*)&sC[si][n0 + 4];
            float yp;
            hst[0] = fmaf(hst[0], dAv, dtx * b0.x); yp  = hst[0] * c0.x;
            hst[1] = fmaf(hst[1], dAv, dtx * b0.y); yp += hst[1] * c0.y;
            hst[2] = fmaf(hst[2], dAv, dtx * b0.z); yp += hst[2] * c0.z;
            hst[3] = fmaf(hst[3], dAv, dtx * b0.w); yp += hst[3] * c0.w;
            hst[4] = fmaf(hst[4], dAv, dtx * b1.x); yp += hst[4] * c1.x;
            hst[5] = fmaf(hst[5], dAv, dtx * b1.y); yp += hst[5] * c1.y;
            hst[6] = fmaf(hst[6], dAv, dtx * b1.z); yp += hst[6] * c1.z;
            hst[7] = fmaf(hst[7], dAv, dtx * b1.w); yp += hst[7] * c1.w;
            yp += __shfl_xor_sync(0xffffffffu, yp, 1);
            yp += __shfl_xor_sync(0xffffffffu, yp, 2);
            yp += __shfl_xor_sync(0xffffffffu, yp, 4);
            if ((t & 7) == 0)
                g_y[(size_t)(b * SEQ + s0 + si) * DINNER + hh * HEADDIM + pb + lp] =
                    yp + Dh * xv;
        }
        __syncthreads();
    }

    size_t st = (((size_t)bz * NCHUNK + chunk) * HEADDIM + (pb + lp)) * DSTATE + n0;
    *(float4*)&g_state[st]     = make_float4(hst[0], hst[1], hst[2], hst[3]);
    *(float4*)&g_state[st + 4] = make_float4(hst[4], hst[5], hst[6], hst[7]);
}

// ---------------- pass 2: inter-chunk state scan ----------------
__global__ void __launch_bounds__(256)
state_scan_kernel()
{
    int idx = blockIdx.x * 256 + threadIdx.x;
    int n  = idx & 63;
    int p  = (idx >> 6) & 63;
    int bz = idx >> 12;
    int b  = bz >> 5, hh = bz & (NHEADS - 1);
    size_t base = (size_t)bz * (NCHUNK * HEADDIM * DSTATE) + (size_t)p * DSTATE + n;
    float hs = 0.0f;
#pragma unroll
    for (int c = 1; c < NCHUNK; c++) {
        float P = g_acum[((b * SEQ) + (c - 1) * CHUNK + (CHUNK - 1)) * NHEADS + hh];
        hs = fmaf(P, hs, g_state[base + (size_t)(c - 1) * (HEADDIM * DSTATE)]);
        g_hstart[base + (size_t)c * (HEADDIM * DSTATE)] = hs;
    }
}

// ---------------- pass 3: correction  y[t] += a(t) * (C[t] . h_start) ------
__global__ void __launch_bounds__(256)
scan_correction_kernel()
{
    const int c  = blockIdx.x + 1;        // chunks 1..7
    const int bz = blockIdx.y;
    const int b  = bz >> 5, hh = bz & (NHEADS - 1);
    const int tid = threadIdx.x;

    __shared__ __align__(16) float sHt[DSTATE][HEADDIM + 4];
    __shared__ __align__(16) float sC [CHUNK][DSTATE];
    __shared__ float sa[CHUNK];

    size_t hb = (size_t)bz * (NCHUNK * HEADDIM * DSTATE) + (size_t)c * (HEADDIM * DSTATE);
#pragma unroll
    for (int k = 0; k < 4; k++) {
        int i = tid + k * 256;
        int p = i >> 4, n4 = (i & 15) * 4;
        float4 v = *(const float4*)&g_hstart[hb + (size_t)p * DSTATE + n4];
        sHt[n4 + 0][p] = v.x; sHt[n4 + 1][p] = v.y;
        sHt[n4 + 2][p] = v.z; sHt[n4 + 3][p] = v.w;
    }
    const size_t rowbase = (size_t)(b * SEQ) * CONVDIM;
#pragma unroll
    for (int k = 0; k < 4; k++) {
        int i = tid + k * 256;
        int tt = i >> 4, n4 = (i & 15) * 4;
        *(float4*)&sC[tt][n4] =
            *(const float4*)&g_xc[rowbase + (size_t)(c * CHUNK + tt) * CONVDIM
                                  + DINNER + DSTATE + n4];
    }
    if (tid < CHUNK)
        sa[tid] = g_acum[(b * SEQ + c * CHUNK + tid) * NHEADS + hh];
    __syncthreads();

#pragma unroll
    for (int it = 0; it < 4; it++) {
        int o  = tid + it * 256;
        int tt = o >> 4, p4 = (o & 15) * 4;
        float4 acc = make_float4(0.f, 0.f, 0.f, 0.f);
#pragma unroll 8
        for (int n = 0; n < DSTATE; n++) {
            float  cv = sC[tt][n];
            float4 hv = *(const float4*)&sHt[n][p4];
            acc.x = fmaf(cv, hv.x, acc.x);
            acc.y = fmaf(cv, hv.y, acc.y);
            acc.z = fmaf(cv, hv.z, acc.z);
            acc.w = fmaf(cv, hv.w, acc.w);
        }
        float at = sa[tt];
        size_t yi = (size_t)(b * SEQ + c * CHUNK + tt) * DINNER + hh * HEADDIM + p4;
        float4 y = *(float4*)&g_y[yi];
        y.x = fmaf(at, acc.x, y.x);
        y.y = fmaf(at, acc.y, y.y);
        y.z = fmaf(at, acc.z, y.z);
        y.w = fmaf(at, acc.w, y.w);
        *(float4*)&g_y[yi] = y;
    }
}

// ---------------- gate (silu(z)) + RMSNorm ----------------
__global__ void __launch_bounds__(256)
gate_norm_kernel(const float* __restrict__ norm_w)
{
    const int t = blockIdx.x;
    __shared__ float sg[DINNER];
    __shared__ float ssum[8];

    float local = 0.0f;
    for (int i = threadIdx.x; i < DINNER; i += 256) {
        float z = g_zx[(size_t)t * EPROJ + i];
        float g = g_y[(size_t)t * DINNER + i] * siluf(z);
        sg[i] = g;
        local = fmaf(g, g, local);
    }
#pragma unroll
    for (int off = 16; off; off >>= 1)
        local += __shfl_xor_sync(0xffffffffu, local, off);
    if ((threadIdx.x & 31) == 0) ssum[threadIdx.x >> 5] = local;
    __syncthreads();
    if (threadIdx.x < 8) {
        float v = ssum[threadIdx.x];
#pragma unroll
        for (int off = 4; off; off >>= 1)
            v += __shfl_xor_sync(0xffu, v, off);
        if (threadIdx.x == 0) ssum[0] = v;
    }
    __syncthreads();
    float scale = rsqrtf(ssum[0] / (float)DINNER + RMS_EPS);
    for (int i = threadIdx.x; i < DINNER; i += 256)
        g_nrm[(size_t)t * DINNER + i] = sg[i] * scale * norm_w[i];
}

// ---------------- decoders ----------------
__global__ void __launch_bounds__(128)
dec_cur_kernel(const float* __restrict__ w, const float* __restrict__ bias,
               float* __restrict__ out)
{
    int o = blockIdx.x * 4 + (threadIdx.x >> 5);   // 0..3071
    int lane = threadIdx.x & 31;
    int tok = o / VNUM, v = o % VNUM;
    const float* hr = &g_h[(size_t)tok * DMODEL];
    const float* wr = &w[v * DMODEL];
    float acc = 0.0f;
    for (int d = lane; d < DMODEL; d += 32) acc = fmaf(hr[d], wr[d], acc);
#pragma unroll
    for (int off = 16; off; off >>= 1)
        acc += __shfl_xor_sync(0xffffffffu, acc, off);
    if (lane == 0) out[o] = acc + bias[v];
}

__global__ void __launch_bounds__(128)
dec_fut_kernel(const float* __restrict__ w, const float* __restrict__ bias,
               float* __restrict__ out)
{
    int o = blockIdx.x * 4 + (threadIdx.x >> 5);   // 0..119
    int lane = threadIdx.x & 31;
    int b = o / (HORIZON * VNUM), j = o % (HORIZON * VNUM);
    const float* hr = &g_h[(size_t)(b * SEQ + (SEQ - 1)) * DMODEL];
    const float* wr = &w[j * DMODEL];
    float acc = 0.0f;
    for (int d = lane; d < DMODEL; d += 32) acc = fmaf(hr[d], wr[d], acc);
#pragma unroll
    for (int off = 16; off; off >>= 1)
        acc += __shfl_xor_sync(0xffffffffu, acc, off);
    if (lane == 0) out[BATCH * SEQ * VNUM + o] = acc + bias[j];
}

// ---------------- launch ----------------
extern "C" void kernel_launch(void* const* d_in, const int* in_sizes, int n_in,
                              void* d_out, int out_size)
{
    const float* embed      = (const float*)d_in[0];
    const float* in_proj_w  = (const float*)d_in[1];
    const float* conv_w     = (const float*)d_in[2];
    const float* conv_b     = (const float*)d_in[3];
    const float* dt_bias    = (const float*)d_in[4];
    const float* A_log      = (const float*)d_in[5];
    const float* Dp         = (const float*)d_in[6];
    const float* norm_w     = (const float*)d_in[7];
    const float* out_proj_w = (const float*)d_in[8];
    const float* dec_cur_w  = (const float*)d_in[9];
    const float* dec_cur_b  = (const float*)d_in[10];
    const float* dec_fut_w  = (const float*)d_in[11];
    const float* dec_fut_b  = (const float*)d_in[12];
    float* out = (float*)d_out;

    float *zx, *nrm, *h;
    cudaGetSymbolAddress((void**)&zx,  g_zx);
    cudaGetSymbolAddress((void**)&nrm, g_nrm);
    cudaGetSymbolAddress((void**)&h,   g_h);

    cudaFuncSetAttribute(gemm_tf32, cudaFuncAttributeMaxDynamicSharedMemorySize,
                         GEMM_SMEM_BYTES);

    // 1) in_proj: [1024,1024] x [4256,1024]^T -> [1024,4256]  (tf32 TC, 3-stage)
    {
        dim3 grid((EPROJ + TBN - 1) / TBN, NTOK / TBM);   // 67 x 8
        gemm_tf32<<<grid, 256, GEMM_SMEM_BYTES>>>(embed, in_proj_w, zx,
                                                  NTOK, EPROJ, DMODEL);
    }
    // 2) causal conv + silu
    conv_silu_kernel<<<(NTOK * CONVDIM + 255) / 256, 256>>>(conv_w, conv_b);
    // 3) dt / la / dA
    dt_kernel<<<(NTOK * NHEADS + 255) / 256, 256>>>(dt_bias, A_log);
    // 3b) within-chunk cumulative dA (warp log-scan)
    acum_kernel<<<64, 256>>>();
    // 4a) intra-chunk scan
    {
        dim3 grid(4, NCHUNK, BATCH * NHEADS);
        scan_chunk_kernel<<<grid, 128>>>(Dp);
    }
    // 4b) inter-chunk state scan
    state_scan_kernel<<<(BATCH * NHEADS * HEADDIM * DSTATE) / 256, 256>>>();
    // 4c) correction
    {
        dim3 grid(NCHUNK - 1, BATCH * NHEADS);
        scan_correction_kernel<<<grid, 256>>>();
    }
    // 5) gate + rmsnorm
    gate_norm_kernel<<<NTOK, 256>>>(norm_w);
    // 6) out_proj: [1024,2048] x [1024,2048]^T -> [1024,1024]  (tf32 TC, 3-stage)
    {
        dim3 grid(DMODEL / TBN, NTOK / TBM);              // 16 x 8
        gemm_tf32<<<grid, 256, GEMM_SMEM_BYTES>>>(nrm, out_proj_w, h,
                                                  NTOK, DMODEL, DINNER);
    }
    // 7) decoders
    dec_cur_kernel<<<(NTOK * VNUM) / 4, 128>>>(dec_cur_w, dec_cur_b, out);
    dec_fut_kernel<<<(BATCH * HORIZON * VNUM) / 4, 128>>>(dec_fut_w, dec_fut_b, out);
}

// round 11
// speedup vs baseline: 1.3395x; 1.3395x over previous
#include <cuda_runtime.h>
#include <math.h>
#include <stdint.h>

// ---------------- problem constants ----------------
#define BATCH   2
#define SEQ     512
#define NTOK    (BATCH*SEQ)          // 1024
#define DMODEL  1024
#define DINNER  2048
#define DSTATE  64
#define HEADDIM 64
#define NHEADS  32
#define CONVDIM (DINNER + 2*DSTATE)  // 2176
#define EPROJ   (2*DINNER + 2*DSTATE + NHEADS) // 4256
#define DCONV   4
#define VNUM    3
#define HORIZON 20
#define RMS_EPS 1e-5f
#define CHUNK   64
#define NCHUNK  (SEQ/CHUNK)          // 8

// ---------------- device scratch (no cudaMalloc allowed) ----------------
__device__ float g_zx    [NTOK * EPROJ];    // in_proj output
__device__ float g_xc    [NTOK * CONVDIM];  // conv+silu output
__device__ float g_dt    [NTOK * NHEADS];   // softplus(dt)
__device__ float g_la    [NTOK * NHEADS];   // dt * A  (log of dA)
__device__ float g_dA    [NTOK * NHEADS];   // exp(dt*A)
__device__ float g_acum  [NTOK * NHEADS];   // within-chunk cumprod of dA
__device__ float g_state [BATCH*NHEADS*NCHUNK*HEADDIM*DSTATE]; // chunk-local end states
__device__ float g_hstart[BATCH*NHEADS*NCHUNK*HEADDIM*DSTATE]; // state at chunk start
__device__ float g_y     [NTOK * DINNER];   // scan output + D*x
__device__ float g_nrm   [NTOK * DINNER];   // gated + rmsnormed
__device__ float g_h     [NTOK * DMODEL];   // out_proj output

__device__ __forceinline__ float siluf(float x) { return x / (1.0f + expf(-x)); }
__device__ __forceinline__ float softplusf(float x) {
    return (x > 20.0f) ? x : log1pf(expf(x));
}

// ---------------- cp.async helpers ----------------
__device__ __forceinline__ void cp_async16(void* smem, const void* gmem) {
    unsigned saddr = (unsigned)__cvta_generic_to_shared(smem);
    asm volatile("cp.async.cg.shared.global [%0], [%1], 16;\n" :: "r"(saddr), "l"(gmem));
}
__device__ __forceinline__ void cp_commit() {
    asm volatile("cp.async.commit_group;\n");
}
template <int N>
__device__ __forceinline__ void cp_wait() {
    asm volatile("cp.async.wait_group %0;\n" :: "n"(N));
}

// ---------------- tf32 raw-mma GEMM NT (3-stage cp.async ring) ------------
// C[M,N] = A[M,K] * B[N,K]^T. A row-major MxK, B row-major NxK.
// BM=128, BN=64, BK=32; 256 threads = 8 warps (4m x 2n), warp tile 32x32
// built from 2x4 mma.sync.m16n8k8.tf32 fragments.
// Smem row stride TLD=36 floats (== 4 mod 32 banks) -> fragment loads
// hit all 32 banks (addr bank = (4*row + col) mod 32), conflict-free.
#define TBM 128
#define TBN 64
#define TBK 32
#define TLD 36
#define STAGES 3
#define AS_STRIDE (TBM*TLD)              // 4608 floats / stage
#define BS_STRIDE (TBN*TLD)              // 2304 floats / stage
#define GEMM_SMEM_BYTES (STAGES*(AS_STRIDE+BS_STRIDE)*4)   // 82944 B

__device__ __forceinline__ uint32_t f2tf32(float f) {
    uint32_t u;
    asm("cvt.rna.tf32.f32 %0, %1;\n" : "=r"(u) : "f"(f));
    return u;
}

__device__ __forceinline__ void mma_tf32(float4& d,
                                         const uint32_t a0, const uint32_t a1,
                                         const uint32_t a2, const uint32_t a3,
                                         const uint32_t b0, const uint32_t b1) {
    asm volatile(
        "mma.sync.aligned.m16n8k8.row.col.f32.tf32.tf32.f32 "
        "{%0,%1,%2,%3}, {%4,%5,%6,%7}, {%8,%9}, {%0,%1,%2,%3};\n"
        : "+f"(d.x), "+f"(d.y), "+f"(d.z), "+f"(d.w)
        : "r"(a0), "r"(a1), "r"(a2), "r"(a3), "r"(b0), "r"(b1));
}

__global__ void __launch_bounds__(256)
gemm_tf32(const float* __restrict__ A, const float* __restrict__ B,
          float* __restrict__ C, int M, int N, int K)
{
    extern __shared__ __align__(16) float smem[];
    float* As = smem;                         // [STAGES][TBM][TLD]
    float* Bs = smem + STAGES * AS_STRIDE;    // [STAGES][TBN][TLD]

    const int tid  = threadIdx.x;
    const int lane = tid & 31;
    const int warp = tid >> 5;
    const int wm   = (warp & 3) * 32;    // 4 warps over M
    const int wn   = (warp >> 2) * 32;   // 2 warps over N
    const int m0   = blockIdx.y * TBM;
    const int n0   = blockIdx.x * TBN;

    float4 acc[2][4];
#pragma unroll
    for (int i = 0; i < 2; i++)
#pragma unroll
        for (int j = 0; j < 4; j++) acc[i][j] = make_float4(0.f, 0.f, 0.f, 0.f);

    const int ntiles = K / TBK;

    // --- async copy of K-tile kt into ring stage stg ---
    auto issue_tile = [&](int kt, int stg) {
        const size_t ko = (size_t)kt * TBK;
        float* as = As + stg * AS_STRIDE;
        float* bs = Bs + stg * BS_STRIDE;
#pragma unroll
        for (int k = 0; k < 4; k++) {            // 1024 float4 slots for A
            int slot = tid + k * 256;
            int r = slot >> 3, c = (slot & 7) * 4;
            cp_async16(&as[r * TLD + c], A + (size_t)(m0 + r) * K + ko + c);
        }
#pragma unroll
        for (int k = 0; k < 2; k++) {            // 512 float4 slots for B
            int slot = tid + k * 256;
            int r = slot >> 3, c = (slot & 7) * 4;
            int rr = (n0 + r < N) ? (n0 + r) : (N - 1);   // clamp; masked at store
            cp_async16(&bs[r * TLD + c], B + (size_t)rr * K + ko + c);
        }
        cp_commit();
    };

    // prologue: two stages in flight
    issue_tile(0, 0);
    if (ntiles > 1) issue_tile(1, 1);

    const int lr = lane >> 2;       // 0..7
    const int lc = lane & 3;        // 0..3

    for (int kt = 0; kt < ntiles; kt++) {
        if (kt + 1 == ntiles) cp_wait<0>(); else cp_wait<1>();
        __syncthreads();                   // tile kt resident; kt-1 compute done
        if (kt + STAGES - 1 < ntiles)
            issue_tile(kt + STAGES - 1, (kt + STAGES - 1) % STAGES);

        const float* Asb = As + (kt % STAGES) * AS_STRIDE;
        const float* Bsb = Bs + (kt % STAGES) * BS_STRIDE;

#pragma unroll
        for (int ks = 0; ks < TBK / 8; ks++) {
            const int kc = ks * 8 + lc;
            // A fragments: rows wm + i*16 + {lr, lr+8}, cols {kc, kc+4}
            uint32_t af[2][4];
#pragma unroll
            for (int i = 0; i < 2; i++) {
                const float* ap = Asb + (size_t)(wm + i * 16 + lr) * TLD;
                af[i][0] = f2tf32(ap[kc]);
                af[i][1] = f2tf32(ap[8 * TLD + kc]);
                af[i][2] = f2tf32(ap[kc + 4]);
                af[i][3] = f2tf32(ap[8 * TLD + kc + 4]);
            }
            // B fragments: cols wn + j*8 + lr, k-rows {kc, kc+4}
            uint32_t bf[4][2];
#pragma unroll
            for (int j = 0; j < 4; j++) {
                const float* bp = Bsb + (size_t)(wn + j * 8 + lr) * TLD;
                bf[j][0] = f2tf32(bp[kc]);
                bf[j][1] = f2tf32(bp[kc + 4]);
            }
#pragma unroll
            for (int i = 0; i < 2; i++)
#pragma unroll
                for (int j = 0; j < 4; j++)
                    mma_tf32(acc[i][j], af[i][0], af[i][1], af[i][2], af[i][3],
                             bf[j][0], bf[j][1]);
        }
    }

    // epilogue: c-frag layout: c0/c1 at (row lr, cols 2*lc, 2*lc+1); c2/c3 at row lr+8
#pragma unroll
    for (int i = 0; i < 2; i++)
#pragma unroll
        for (int j = 0; j < 4; j++) {
            int r  = m0 + wm + i * 16 + lr;
            int cn = n0 + wn + j * 8 + lc * 2;
            if (cn < N) {   // N even, cn even -> cn+1 < N as well
                *(float2*)&C[(size_t)r * N + cn] =
                    make_float2(acc[i][j].x, acc[i][j].y);
                *(float2*)&C[(size_t)(r + 8) * N + cn] =
                    make_float2(acc[i][j].z, acc[i][j].w);
            }
        }
}

// ---------------- conv (depthwise causal, width 4) + silu ----------------
__global__ void __launch_bounds__(256)
conv_silu_kernel(const float* __restrict__ conv_w, const float* __restrict__ conv_b)
{
    int idx = blockIdx.x * blockDim.x + threadIdx.x;
    if (idx >= NTOK * CONVDIM) return;
    int c = idx % CONVDIM;
    int t = idx / CONVDIM;
    int s = t & (SEQ - 1);
    int b = t >> 9;

    float acc = conv_b[c];
#pragma unroll
    for (int k = 0; k < DCONV; k++) {
        int ss = s + k - (DCONV - 1);
        if (ss >= 0)
            acc = fmaf(conv_w[c * DCONV + k],
                       g_zx[(size_t)(b * SEQ + ss) * EPROJ + DINNER + c], acc);
    }
    g_xc[(size_t)t * CONVDIM + c] = siluf(acc);
}

// ---------------- dt = softplus(dt_raw + bias), la = dt*A, dA = exp(la) ----
__global__ void __launch_bounds__(256)
dt_kernel(const float* __restrict__ dt_bias, const float* __restrict__ A_log)
{
    int idx = blockIdx.x * blockDim.x + threadIdx.x;
    if (idx >= NTOK * NHEADS) return;
    int hh = idx & (NHEADS - 1);
    int t  = idx >> 5;
    float raw = g_zx[(size_t)t * EPROJ + DINNER + CONVDIM + hh];
    float dtv = softplusf(raw + dt_bias[hh]);
    float Ah  = -expf(A_log[hh]);
    float la  = dtv * Ah;
    g_dt[idx] = dtv;
    g_la[idx] = la;
    g_dA[idx] = expf(la);
}

// ---------------- within-chunk cumulative dA via warp log-scan ------------
__global__ void __launch_bounds__(256)
acum_kernel()
{
    int w    = (blockIdx.x * 256 + threadIdx.x) >> 5;   // 0..511
    int lane = threadIdx.x & 31;
    if (w >= BATCH * NHEADS * NCHUNK) return;
    int chunk = w & (NCHUNK - 1);
    int hh    = (w >> 3) & (NHEADS - 1);
    int b     = w >> 8;
    int base  = (b * SEQ + chunk * CHUNK) * NHEADS + hh;

    float l0 = g_la[base + (lane * 2)     * NHEADS];
    float l1 = g_la[base + (lane * 2 + 1) * NHEADS];
    float loc = l0 + l1;
    float sc = loc;
#pragma unroll
    for (int off = 1; off < 32; off <<= 1) {
        float v = __shfl_up_sync(0xffffffffu, sc, off);
        if (lane >= off) sc += v;
    }
    float excl = sc - loc;
    g_acum[base + (lane * 2)     * NHEADS] = expf(excl + l0);
    g_acum[base + (lane * 2 + 1) * NHEADS] = expf(excl + loc);
}

// ---------------- pass 1: intra-chunk scan (zero initial state) ----------------
__global__ void __launch_bounds__(128)
scan_chunk_kernel(const float* __restrict__ Dp)
{
    const int bz = blockIdx.z;
    const int b  = bz >> 5;
    const int hh = bz & (NHEADS - 1);
    const int chunk = blockIdx.y;
    const int pb = blockIdx.x * 16;
    const int t  = threadIdx.x;
    const int lp = t >> 3;
    const int n0 = (t & 7) * 8;

    __shared__ __align__(16) float sB[32][64];
    __shared__ __align__(16) float sC[32][64];
    __shared__ __align__(16) float sX[32][16];
    __shared__ float sdA[32], sdt[32];

    float hst[8];
#pragma unroll
    for (int j = 0; j < 8; j++) hst[j] = 0.0f;

    const float Dh = Dp[hh];
    const size_t rowbase = (size_t)(b * SEQ) * CONVDIM;

#pragma unroll
    for (int sub = 0; sub < 2; sub++) {
        const int s0 = chunk * CHUNK + sub * 32;
        for (int i = t; i < 512; i += 128) {
            int si = i >> 4, j4 = (i & 15) * 4;
            size_t r = rowbase + (size_t)(s0 + si) * CONVDIM;
            *(float4*)&sB[si][j4] = *(const float4*)&g_xc[r + DINNER + j4];
            *(float4*)&sC[si][j4] = *(const float4*)&g_xc[r + DINNER + DSTATE + j4];
        }
        {
            int si = t >> 2, j4 = (t & 3) * 4;
            size_t r = rowbase + (size_t)(s0 + si) * CONVDIM;
            *(float4*)&sX[si][j4] = *(const float4*)&g_xc[r + hh * HEADDIM + pb + j4];
        }
        if (t < 32) {
            int idx = (b * SEQ + s0 + t) * NHEADS + hh;
            sdA[t] = g_dA[idx];
            sdt[t] = g_dt[idx];
        }
        __syncthreads();

        for (int si = 0; si < 32; si++) {
            float dAv = sdA[si];
            float xv  = sX[si][lp];
            float dtx = sdt[si] * xv;
            float4 b0 = *(const float4*)&sB[si][n0];
            float4 b1 = *(const float4*)&sB[si][n0 + 4];
            float4 c0 = *(const float4*)&sC[si][n0];
            float4 c1 = *(const float4*)&sC[si][n0 + 4];
            float yp;
            hst[0] = fmaf(hst[0], dAv, dtx * b0.x); yp  = hst[0] * c0.x;
            hst[1] = fmaf(hst[1], dAv, dtx * b0.y); yp += hst[1] * c0.y;
            hst[2] = fmaf(hst[2], dAv, dtx * b0.z); yp += hst[2] * c0.z;
            hst[3] = fmaf(hst[3], dAv, dtx * b0.w); yp += hst[3] * c0.w;
            hst[4] = fmaf(hst[4], dAv, dtx * b1.x); yp += hst[4] * c1.x;
            hst[5] = fmaf(hst[5], dAv, dtx * b1.y); yp += hst[5] * c1.y;
            hst[6] = fmaf(hst[6], dAv, dtx * b1.z); yp += hst[6] * c1.z;
            hst[7] = fmaf(hst[7], dAv, dtx * b1.w); yp += hst[7] * c1.w;
            yp += __shfl_xor_sync(0xffffffffu, yp, 1);
            yp += __shfl_xor_sync(0xffffffffu, yp, 2);
            yp += __shfl_xor_sync(0xffffffffu, yp, 4);
            if ((t & 7) == 0)
                g_y[(size_t)(b * SEQ + s0 + si) * DINNER + hh * HEADDIM + pb + lp] =
                    yp + Dh * xv;
        }
        __syncthreads();
    }

    size_t st = (((size_t)bz * NCHUNK + chunk) * HEADDIM + (pb + lp)) * DSTATE + n0;
    *(float4*)&g_state[st]     = make_float4(hst[0], hst[1], hst[2], hst[3]);
    *(float4*)&g_state[st + 4] = make_float4(hst[4], hst[5], hst[6], hst[7]);
}

// ---------------- pass 2: inter-chunk state scan ----------------
__global__ void __launch_bounds__(256)
state_scan_kernel()
{
    int idx = blockIdx.x * 256 + threadIdx.x;
    int n  = idx & 63;
    int p  = (idx >> 6) & 63;
    int bz = idx >> 12;
    int b  = bz >> 5, hh = bz & (NHEADS - 1);
    size_t base = (size_t)bz * (NCHUNK * HEADDIM * DSTATE) + (size_t)p * DSTATE + n;
    float hs = 0.0f;
#pragma unroll
    for (int c = 1; c < NCHUNK; c++) {
        float P = g_acum[((b * SEQ) + (c - 1) * CHUNK + (CHUNK - 1)) * NHEADS + hh];
        hs = fmaf(P, hs, g_state[base + (size_t)(c - 1) * (HEADDIM * DSTATE)]);
        g_hstart[base + (size_t)c * (HEADDIM * DSTATE)] = hs;
    }
}

// ---------------- pass 3: correction  y[t] += a(t) * (C[t] . h_start) ------
__global__ void __launch_bounds__(256)
scan_correction_kernel()
{
    const int c  = blockIdx.x + 1;        // chunks 1..7
    const int bz = blockIdx.y;
    const int b  = bz >> 5, hh = bz & (NHEADS - 1);
    const int tid = threadIdx.x;

    __shared__ __align__(16) float sHt[DSTATE][HEADDIM + 4];
    __shared__ __align__(16) float sC [CHUNK][DSTATE];
    __shared__ float sa[CHUNK];

    size_t hb = (size_t)bz * (NCHUNK * HEADDIM * DSTATE) + (size_t)c * (HEADDIM * DSTATE);
#pragma unroll
    for (int k = 0; k < 4; k++) {
        int i = tid + k * 256;
        int p = i >> 4, n4 = (i & 15) * 4;
        float4 v = *(const float4*)&g_hstart[hb + (size_t)p * DSTATE + n4];
        sHt[n4 + 0][p] = v.x; sHt[n4 + 1][p] = v.y;
        sHt[n4 + 2][p] = v.z; sHt[n4 + 3][p] = v.w;
    }
    const size_t rowbase = (size_t)(b * SEQ) * CONVDIM;
#pragma unroll
    for (int k = 0; k < 4; k++) {
        int i = tid + k * 256;
        int tt = i >> 4, n4 = (i & 15) * 4;
        *(float4*)&sC[tt][n4] =
            *(const float4*)&g_xc[rowbase + (size_t)(c * CHUNK + tt) * CONVDIM
                                  + DINNER + DSTATE + n4];
    }
    if (tid < CHUNK)
        sa[tid] = g_acum[(b * SEQ + c * CHUNK + tid) * NHEADS + hh];
    __syncthreads();

#pragma unroll
    for (int it = 0; it < 4; it++) {
        int o  = tid + it * 256;
        int tt = o >> 4, p4 = (o & 15) * 4;
        float4 acc = make_float4(0.f, 0.f, 0.f, 0.f);
#pragma unroll 8
        for (int n = 0; n < DSTATE; n++) {
            float  cv = sC[tt][n];
            float4 hv = *(const float4*)&sHt[n][p4];
            acc.x = fmaf(cv, hv.x, acc.x);
            acc.y = fmaf(cv, hv.y, acc.y);
            acc.z = fmaf(cv, hv.z, acc.z);
            acc.w = fmaf(cv, hv.w, acc.w);
        }
        float at = sa[tt];
        size_t yi = (size_t)(b * SEQ + c * CHUNK + tt) * DINNER + hh * HEADDIM + p4;
        float4 y = *(float4*)&g_y[yi];
        y.x = fmaf(at, acc.x, y.x);
        y.y = fmaf(at, acc.y, y.y);
        y.z = fmaf(at, acc.z, y.z);
        y.w = fmaf(at, acc.w, y.w);
        *(float4*)&g_y[yi] = y;
    }
}

// ---------------- gate (silu(z)) + RMSNorm ----------------
__global__ void __launch_bounds__(256)
gate_norm_kernel(const float* __restrict__ norm_w)
{
    const int t = blockIdx.x;
    __shared__ float sg[DINNER];
    __shared__ float ssum[8];

    float local = 0.0f;
    for (int i = threadIdx.x; i < DINNER; i += 256) {
        float z = g_zx[(size_t)t * EPROJ + i];
        float g = g_y[(size_t)t * DINNER + i] * siluf(z);
        sg[i] = g;
        local = fmaf(g, g, local);
    }
#pragma unroll
    for (int off = 16; off; off >>= 1)
        local += __shfl_xor_sync(0xffffffffu, local, off);
    if ((threadIdx.x & 31) == 0) ssum[threadIdx.x >> 5] = local;
    __syncthreads();
    if (threadIdx.x < 8) {
        float v = ssum[threadIdx.x];
#pragma unroll
        for (int off = 4; off; off >>= 1)
            v += __shfl_xor_sync(0xffu, v, off);
        if (threadIdx.x == 0) ssum[0] = v;
    }
    __syncthreads();
    float scale = rsqrtf(ssum[0] / (float)DINNER + RMS_EPS);
    for (int i = threadIdx.x; i < DINNER; i += 256)
        g_nrm[(size_t)t * DINNER + i] = sg[i] * scale * norm_w[i];
}

// ---------------- decoders ----------------
__global__ void __launch_bounds__(128)
dec_cur_kernel(const float* __restrict__ w, const float* __restrict__ bias,
               float* __restrict__ out)
{
    int o = blockIdx.x * 4 + (threadIdx.x >> 5);   // 0..3071
    int lane = threadIdx.x & 31;
    int tok = o / VNUM, v = o % VNUM;
    const float* hr = &g_h[(size_t)tok * DMODEL];
    const float* wr = &w[v * DMODEL];
    float acc = 0.0f;
    for (int d = lane; d < DMODEL; d += 32) acc = fmaf(hr[d], wr[d], acc);
#pragma unroll
    for (int off = 16; off; off >>= 1)
        acc += __shfl_xor_sync(0xffffffffu, acc, off);
    if (lane == 0) out[o] = acc + bias[v];
}

__global__ void __launch_bounds__(128)
dec_fut_kernel(const float* __restrict__ w, const float* __restrict__ bias,
               float* __restrict__ out)
{
    int o = blockIdx.x * 4 + (threadIdx.x >> 5);   // 0..119
    int lane = threadIdx.x & 31;
    int b = o / (HORIZON * VNUM), j = o % (HORIZON * VNUM);
    const float* hr = &g_h[(size_t)(b * SEQ + (SEQ - 1)) * DMODEL];
    const float* wr = &w[j * DMODEL];
    float acc = 0.0f;
    for (int d = lane; d < DMODEL; d += 32) acc = fmaf(hr[d], wr[d], acc);
#pragma unroll
    for (int off = 16; off; off >>= 1)
        acc += __shfl_xor_sync(0xffffffffu, acc, off);
    if (lane == 0) out[BATCH * SEQ * VNUM + o] = acc + bias[j];
}

// ---------------- launch ----------------
extern "C" void kernel_launch(void* const* d_in, const int* in_sizes, int n_in,
                              void* d_out, int out_size)
{
    const float* embed      = (const float*)d_in[0];
    const float* in_proj_w  = (const float*)d_in[1];
    const float* conv_w     = (const float*)d_in[2];
    const float* conv_b     = (const float*)d_in[3];
    const float* dt_bias    = (const float*)d_in[4];
    const float* A_log      = (const float*)d_in[5];
    const float* Dp         = (const float*)d_in[6];
    const float* norm_w     = (const float*)d_in[7];
    const float* out_proj_w = (const float*)d_in[8];
    const float* dec_cur_w  = (const float*)d_in[9];
    const float* dec_cur_b  = (const float*)d_in[10];
    const float* dec_fut_w  = (const float*)d_in[11];
    const float* dec_fut_b  = (const float*)d_in[12];
    float* out = (float*)d_out;

    float *zx, *nrm, *h;
    cudaGetSymbolAddress((void**)&zx,  g_zx);
    cudaGetSymbolAddress((void**)&nrm, g_nrm);
    cudaGetSymbolAddress((void**)&h,   g_h);

    cudaFuncSetAttribute(gemm_tf32, cudaFuncAttributeMaxDynamicSharedMemorySize,
                         GEMM_SMEM_BYTES);

    // 1) in_proj: [1024,1024] x [4256,1024]^T -> [1024,4256]  (raw mma tf32)
    {
        dim3 grid((EPROJ + TBN - 1) / TBN, NTOK / TBM);   // 67 x 8
        gemm_tf32<<<grid, 256, GEMM_SMEM_BYTES>>>(embed, in_proj_w, zx,
                                                  NTOK, EPROJ, DMODEL);
    }
    // 2) causal conv + silu
    conv_silu_kernel<<<(NTOK * CONVDIM + 255) / 256, 256>>>(conv_w, conv_b);
    // 3) dt / la / dA
    dt_kernel<<<(NTOK * NHEADS + 255) / 256, 256>>>(dt_bias, A_log);
    // 3b) within-chunk cumulative dA (warp log-scan)
    acum_kernel<<<64, 256>>>();
    // 4a) intra-chunk scan
    {
        dim3 grid(4, NCHUNK, BATCH * NHEADS);
        scan_chunk_kernel<<<grid, 128>>>(Dp);
    }
    // 4b) inter-chunk state scan
    state_scan_kernel<<<(BATCH * NHEADS * HEADDIM * DSTATE) / 256, 256>>>();
    // 4c) correction
    {
        dim3 grid(NCHUNK - 1, BATCH * NHEADS);
        scan_correction_kernel<<<grid, 256>>>();
    }
    // 5) gate + rmsnorm
    gate_norm_kernel<<<NTOK, 256>>>(norm_w);
    // 6) out_proj: [1024,2048] x [1024,2048]^T -> [1024,1024]  (raw mma tf32)
    {
        dim3 grid(DMODEL / TBN, NTOK / TBM);              // 16 x 8
        gemm_tf32<<<grid, 256, GEMM_SMEM_BYTES>>>(nrm, out_proj_w, h,
                                                  NTOK, DMODEL, DINNER);
    }
    // 7) decoders
    dec_cur_kernel<<<(NTOK * VNUM) / 4, 128>>>(dec_cur_w, dec_cur_b, out);
    dec_fut_kernel<<<(BATCH * HORIZON * VNUM) / 4, 128>>>(dec_fut_w, dec_fut_b, out);
}

// round 12
// speedup vs baseline: 1.4457x; 1.0793x over previous
#include <cuda_runtime.h>
#include <math.h>
#include <stdint.h>

// ---------------- problem constants ----------------
#define BATCH   2
#define SEQ     512
#define NTOK    (BATCH*SEQ)          // 1024
#define DMODEL  1024
#define DINNER  2048
#define DSTATE  64
#define HEADDIM 64
#define NHEADS  32
#define CONVDIM (DINNER + 2*DSTATE)  // 2176
#define EPROJ   (2*DINNER + 2*DSTATE + NHEADS) // 4256
#define DCONV   4
#define VNUM    3
#define HORIZON 20
#define RMS_EPS 1e-5f
#define CHUNK   64
#define NCHUNK  (SEQ/CHUNK)          // 8

// ---------------- device scratch (no cudaMalloc allowed) ----------------
__device__ float g_zx    [NTOK * EPROJ];    // in_proj output
__device__ float g_xc    [NTOK * CONVDIM];  // conv+silu output
__device__ float g_dt    [NTOK * NHEADS];   // softplus(dt)
__device__ float g_la    [NTOK * NHEADS];   // dt * A  (log of dA)
__device__ float g_dA    [NTOK * NHEADS];   // exp(dt*A)
__device__ float g_acum  [NTOK * NHEADS];   // within-chunk cumprod of dA
__device__ float g_state [BATCH*NHEADS*NCHUNK*HEADDIM*DSTATE]; // chunk-local end states
__device__ float g_hstart[BATCH*NHEADS*NCHUNK*HEADDIM*DSTATE]; // state at chunk start
__device__ float g_y     [NTOK * DINNER];   // scan output + D*x
__device__ float g_nrm   [NTOK * DINNER];   // gated + rmsnormed (tf32-rounded)
__device__ float g_h     [NTOK * DMODEL];   // out_proj output
// tf32-rounded GEMM operands (rounding hoisted out of the mma inner loop)
__device__ float g_rA    [NTOK * DMODEL];   // rounded embed
__device__ float g_rW1   [EPROJ * DMODEL];  // rounded in_proj_w
__device__ float g_rW2   [DMODEL * DINNER]; // rounded out_proj_w

__device__ __forceinline__ float siluf(float x) { return x / (1.0f + expf(-x)); }
__device__ __forceinline__ float softplusf(float x) {
    return (x > 20.0f) ? x : log1pf(expf(x));
}

__device__ __forceinline__ float tf32r(float f) {
    uint32_t u;
    asm("cvt.rna.tf32.f32 %0, %1;\n" : "=r"(u) : "f"(f));
    return __uint_as_float(u);
}

// ---------------- cp.async helpers ----------------
__device__ __forceinline__ void cp_async16(void* smem, const void* gmem) {
    unsigned saddr = (unsigned)__cvta_generic_to_shared(smem);
    asm volatile("cp.async.cg.shared.global [%0], [%1], 16;\n" :: "r"(saddr), "l"(gmem));
}
__device__ __forceinline__ void cp_commit() {
    asm volatile("cp.async.commit_group;\n");
}
template <int N>
__device__ __forceinline__ void cp_wait() {
    asm volatile("cp.async.wait_group %0;\n" :: "n"(N));
}

// ---------------- elementwise tf32 rounding pass ----------------
__global__ void __launch_bounds__(256)
round_tf32_kernel(const float* __restrict__ in, float* __restrict__ out, int n4)
{
    int i = blockIdx.x * 256 + threadIdx.x;
    if (i >= n4) return;
    float4 v = *(const float4*)&in[i * 4];
    v.x = tf32r(v.x); v.y = tf32r(v.y); v.z = tf32r(v.z); v.w = tf32r(v.w);
    *(float4*)&out[i * 4] = v;
}

// ---------------- tf32 raw-mma GEMM NT (3-stage cp.async ring) ------------
// C[M,N] = A[M,K] * B[N,K]^T. Operands PRE-ROUNDED to tf32 (no in-loop cvt).
// BM=128, BN=64, BK=32; 256 threads = 8 warps (4m x 2n), warp tile 32x32.
// Smem row stride TLD=36 floats -> fragment loads conflict-free.
#define TBM 128
#define TBN 64
#define TBK 32
#define TLD 36
#define STAGES 3
#define AS_STRIDE (TBM*TLD)              // 4608 floats / stage
#define BS_STRIDE (TBN*TLD)              // 2304 floats / stage
#define GEMM_SMEM_BYTES (STAGES*(AS_STRIDE+BS_STRIDE)*4)   // 82944 B

__device__ __forceinline__ void mma_tf32(float4& d,
                                         const uint32_t a0, const uint32_t a1,
                                         const uint32_t a2, const uint32_t a3,
                                         const uint32_t b0, const uint32_t b1) {
    asm volatile(
        "mma.sync.aligned.m16n8k8.row.col.f32.tf32.tf32.f32 "
        "{%0,%1,%2,%3}, {%4,%5,%6,%7}, {%8,%9}, {%0,%1,%2,%3};\n"
        : "+f"(d.x), "+f"(d.y), "+f"(d.z), "+f"(d.w)
        : "r"(a0), "r"(a1), "r"(a2), "r"(a3), "r"(b0), "r"(b1));
}

__global__ void __launch_bounds__(256, 2)
gemm_tf32(const float* __restrict__ A, const float* __restrict__ B,
          float* __restrict__ C, int M, int N, int K)
{
    extern __shared__ __align__(16) float smem[];
    float* As = smem;                         // [STAGES][TBM][TLD]
    float* Bs = smem + STAGES * AS_STRIDE;    // [STAGES][TBN][TLD]

    const int tid  = threadIdx.x;
    const int lane = tid & 31;
    const int warp = tid >> 5;
    const int wm   = (warp & 3) * 32;    // 4 warps over M
    const int wn   = (warp >> 2) * 32;   // 2 warps over N
    const int m0   = blockIdx.y * TBM;
    const int n0   = blockIdx.x * TBN;

    float4 acc[2][4];
#pragma unroll
    for (int i = 0; i < 2; i++)
#pragma unroll
        for (int j = 0; j < 4; j++) acc[i][j] = make_float4(0.f, 0.f, 0.f, 0.f);

    const int ntiles = K / TBK;

    auto issue_tile = [&](int kt, int stg) {
        const size_t ko = (size_t)kt * TBK;
        float* as = As + stg * AS_STRIDE;
        float* bs = Bs + stg * BS_STRIDE;
#pragma unroll
        for (int k = 0; k < 4; k++) {            // 1024 float4 slots for A
            int slot = tid + k * 256;
            int r = slot >> 3, c = (slot & 7) * 4;
            cp_async16(&as[r * TLD + c], A + (size_t)(m0 + r) * K + ko + c);
        }
#pragma unroll
        for (int k = 0; k < 2; k++) {            // 512 float4 slots for B
            int slot = tid + k * 256;
            int r = slot >> 3, c = (slot & 7) * 4;
            int rr = (n0 + r < N) ? (n0 + r) : (N - 1);   // clamp; masked at store
            cp_async16(&bs[r * TLD + c], B + (size_t)rr * K + ko + c);
        }
        cp_commit();
    };

    issue_tile(0, 0);
    if (ntiles > 1) issue_tile(1, 1);

    const int lr = lane >> 2;       // 0..7
    const int lc = lane & 3;        // 0..3

    for (int kt = 0; kt < ntiles; kt++) {
        if (kt + 1 == ntiles) cp_wait<0>(); else cp_wait<1>();
        __syncthreads();
        if (kt + STAGES - 1 < ntiles)
            issue_tile(kt + STAGES - 1, (kt + STAGES - 1) % STAGES);

        const float* Asb = As + (kt % STAGES) * AS_STRIDE;
        const float* Bsb = Bs + (kt % STAGES) * BS_STRIDE;

#pragma unroll
        for (int ks = 0; ks < TBK / 8; ks++) {
            const int kc = ks * 8 + lc;
            uint32_t af[2][4];
#pragma unroll
            for (int i = 0; i < 2; i++) {
                const float* ap = Asb + (size_t)(wm + i * 16 + lr) * TLD;
                af[i][0] = __float_as_uint(ap[kc]);
                af[i][1] = __float_as_uint(ap[8 * TLD + kc]);
                af[i][2] = __float_as_uint(ap[kc + 4]);
                af[i][3] = __float_as_uint(ap[8 * TLD + kc + 4]);
            }
            uint32_t bf[4][2];
#pragma unroll
            for (int j = 0; j < 4; j++) {
                const float* bp = Bsb + (size_t)(wn + j * 8 + lr) * TLD;
                bf[j][0] = __float_as_uint(bp[kc]);
                bf[j][1] = __float_as_uint(bp[kc + 4]);
            }
#pragma unroll
            for (int i = 0; i < 2; i++)
#pragma unroll
                for (int j = 0; j < 4; j++)
                    mma_tf32(acc[i][j], af[i][0], af[i][1], af[i][2], af[i][3],
                             bf[j][0], bf[j][1]);
        }
    }

#pragma unroll
    for (int i = 0; i < 2; i++)
#pragma unroll
        for (int j = 0; j < 4; j++) {
            int r  = m0 + wm + i * 16 + lr;
            int cn = n0 + wn + j * 8 + lc * 2;
            if (cn < N) {
                *(float2*)&C[(size_t)r * N + cn] =
                    make_float2(acc[i][j].x, acc[i][j].y);
                *(float2*)&C[(size_t)(r + 8) * N + cn] =
                    make_float2(acc[i][j].z, acc[i][j].w);
            }
        }
}

// ---------------- conv (depthwise causal, width 4) + silu ----------------
__global__ void __launch_bounds__(256)
conv_silu_kernel(const float* __restrict__ conv_w, const float* __restrict__ conv_b)
{
    int idx = blockIdx.x * blockDim.x + threadIdx.x;
    if (idx >= NTOK * CONVDIM) return;
    int c = idx % CONVDIM;
    int t = idx / CONVDIM;
    int s = t & (SEQ - 1);
    int b = t >> 9;

    float acc = conv_b[c];
#pragma unroll
    for (int k = 0; k < DCONV; k++) {
        int ss = s + k - (DCONV - 1);
        if (ss >= 0)
            acc = fmaf(conv_w[c * DCONV + k],
                       g_zx[(size_t)(b * SEQ + ss) * EPROJ + DINNER + c], acc);
    }
    g_xc[(size_t)t * CONVDIM + c] = siluf(acc);
}

// ---------------- dt = softplus(dt_raw + bias), la = dt*A, dA = exp(la) ----
__global__ void __launch_bounds__(256)
dt_kernel(const float* __restrict__ dt_bias, const float* __restrict__ A_log)
{
    int idx = blockIdx.x * blockDim.x + threadIdx.x;
    if (idx >= NTOK * NHEADS) return;
    int hh = idx & (NHEADS - 1);
    int t  = idx >> 5;
    float raw = g_zx[(size_t)t * EPROJ + DINNER + CONVDIM + hh];
    float dtv = softplusf(raw + dt_bias[hh]);
    float Ah  = -expf(A_log[hh]);
    float la  = dtv * Ah;
    g_dt[idx] = dtv;
    g_la[idx] = la;
    g_dA[idx] = expf(la);
}

// ---------------- within-chunk cumulative dA via warp log-scan ------------
__global__ void __launch_bounds__(256)
acum_kernel()
{
    int w    = (blockIdx.x * 256 + threadIdx.x) >> 5;   // 0..511
    int lane = threadIdx.x & 31;
    if (w >= BATCH * NHEADS * NCHUNK) return;
    int chunk = w & (NCHUNK - 1);
    int hh    = (w >> 3) & (NHEADS - 1);
    int b     = w >> 8;
    int base  = (b * SEQ + chunk * CHUNK) * NHEADS + hh;

    float l0 = g_la[base + (lane * 2)     * NHEADS];
    float l1 = g_la[base + (lane * 2 + 1) * NHEADS];
    float loc = l0 + l1;
    float sc = loc;
#pragma unroll
    for (int off = 1; off < 32; off <<= 1) {
        float v = __shfl_up_sync(0xffffffffu, sc, off);
        if (lane >= off) sc += v;
    }
    float excl = sc - loc;
    g_acum[base + (lane * 2)     * NHEADS] = expf(excl + l0);
    g_acum[base + (lane * 2 + 1) * NHEADS] = expf(excl + loc);
}

// ---------------- pass 1: intra-chunk scan (zero initial state) ----------------
__global__ void __launch_bounds__(128)
scan_chunk_kernel(const float* __restrict__ Dp)
{
    const int bz = blockIdx.z;
    const int b  = bz >> 5;
    const int hh = bz & (NHEADS - 1);
    const int chunk = blockIdx.y;
    const int pb = blockIdx.x * 16;
    const int t  = threadIdx.x;
    const int lp = t >> 3;
    const int n0 = (t & 7) * 8;

    __shared__ __align__(16) float sB[32][64];
    __shared__ __align__(16) float sC[32][64];
    __shared__ __align__(16) float sX[32][16];
    __shared__ float sdA[32], sdt[32];

    float hst[8];
#pragma unroll
    for (int j = 0; j < 8; j++) hst[j] = 0.0f;

    const float Dh = Dp[hh];
    const size_t rowbase = (size_t)(b * SEQ) * CONVDIM;

#pragma unroll
    for (int sub = 0; sub < 2; sub++) {
        const int s0 = chunk * CHUNK + sub * 32;
        for (int i = t; i < 512; i += 128) {
            int si = i >> 4, j4 = (i & 15) * 4;
            size_t r = rowbase + (size_t)(s0 + si) * CONVDIM;
            *(float4*)&sB[si][j4] = *(const float4*)&g_xc[r + DINNER + j4];
            *(float4*)&sC[si][j4] = *(const float4*)&g_xc[r + DINNER + DSTATE + j4];
        }
        {
            int si = t >> 2, j4 = (t & 3) * 4;
            size_t r = rowbase + (size_t)(s0 + si) * CONVDIM;
            *(float4*)&sX[si][j4] = *(const float4*)&g_xc[r + hh * HEADDIM + pb + j4];
        }
        if (t < 32) {
            int idx = (b * SEQ + s0 + t) * NHEADS + hh;
            sdA[t] = g_dA[idx];
            sdt[t] = g_dt[idx];
        }
        __syncthreads();

        for (int si = 0; si < 32; si++) {
            float dAv = sdA[si];
            float xv  = sX[si][lp];
            float dtx = sdt[si] * xv;
            float4 b0 = *(const float4*)&sB[si][n0];
            float4 b1 = *(const float4*)&sB[si][n0 + 4];
            float4 c0 = *(const float4*)&sC[si][n0];
            float4 c1 = *(const float4*)&sC[si][n0 + 4];
            float yp;
            hst[0] = fmaf(hst[0], dAv, dtx * b0.x); yp  = hst[0] * c0.x;
            hst[1] = fmaf(hst[1], dAv, dtx * b0.y); yp += hst[1] * c0.y;
            hst[2] = fmaf(hst[2], dAv, dtx * b0.z); yp += hst[2] * c0.z;
            hst[3] = fmaf(hst[3], dAv, dtx * b0.w); yp += hst[3] * c0.w;
            hst[4] = fmaf(hst[4], dAv, dtx * b1.x); yp += hst[4] * c1.x;
            hst[5] = fmaf(hst[5], dAv, dtx * b1.y); yp += hst[5] * c1.y;
            hst[6] = fmaf(hst[6], dAv, dtx * b1.z); yp += hst[6] * c1.z;
            hst[7] = fmaf(hst[7], dAv, dtx * b1.w); yp += hst[7] * c1.w;
            yp += __shfl_xor_sync(0xffffffffu, yp, 1);
            yp += __shfl_xor_sync(0xffffffffu, yp, 2);
            yp += __shfl_xor_sync(0xffffffffu, yp, 4);
            if ((t & 7) == 0)
                g_y[(size_t)(b * SEQ + s0 + si) * DINNER + hh * HEADDIM + pb + lp] =
                    yp + Dh * xv;
        }
        __syncthreads();
    }

    size_t st = (((size_t)bz * NCHUNK + chunk) * HEADDIM + (pb + lp)) * DSTATE + n0;
    *(float4*)&g_state[st]     = make_float4(hst[0], hst[1], hst[2], hst[3]);
    *(float4*)&g_state[st + 4] = make_float4(hst[4], hst[5], hst[6], hst[7]);
}

// ---------------- pass 2: inter-chunk state scan ----------------
__global__ void __launch_bounds__(256)
state_scan_kernel()
{
    int idx = blockIdx.x * 256 + threadIdx.x;
    int n  = idx & 63;
    int p  = (idx >> 6) & 63;
    int bz = idx >> 12;
    int b  = bz >> 5, hh = bz & (NHEADS - 1);
    size_t base = (size_t)bz * (NCHUNK * HEADDIM * DSTATE) + (size_t)p * DSTATE + n;
    float hs = 0.0f;
#pragma unroll
    for (int c = 1; c < NCHUNK; c++) {
        float P = g_acum[((b * SEQ) + (c - 1) * CHUNK + (CHUNK - 1)) * NHEADS + hh];
        hs = fmaf(P, hs, g_state[base + (size_t)(c - 1) * (HEADDIM * DSTATE)]);
        g_hstart[base + (size_t)c * (HEADDIM * DSTATE)] = hs;
    }
}

// ---------------- pass 3: correction  y[t] += a(t) * (C[t] . h_start) ------
__global__ void __launch_bounds__(256)
scan_correction_kernel()
{
    const int c  = blockIdx.x + 1;        // chunks 1..7
    const int bz = blockIdx.y;
    const int b  = bz >> 5, hh = bz & (NHEADS - 1);
    const int tid = threadIdx.x;

    __shared__ __align__(16) float sHt[DSTATE][HEADDIM + 4];
    __shared__ __align__(16) float sC [CHUNK][DSTATE];
    __shared__ float sa[CHUNK];

    size_t hb = (size_t)bz * (NCHUNK * HEADDIM * DSTATE) + (size_t)c * (HEADDIM * DSTATE);
#pragma unroll
    for (int k = 0; k < 4; k++) {
        int i = tid + k * 256;
        int p = i >> 4, n4 = (i & 15) * 4;
        float4 v = *(const float4*)&g_hstart[hb + (size_t)p * DSTATE + n4];
        sHt[n4 + 0][p] = v.x; sHt[n4 + 1][p] = v.y;
        sHt[n4 + 2][p] = v.z; sHt[n4 + 3][p] = v.w;
    }
    const size_t rowbase = (size_t)(b * SEQ) * CONVDIM;
#pragma unroll
    for (int k = 0; k < 4; k++) {
        int i = tid + k * 256;
        int tt = i >> 4, n4 = (i & 15) * 4;
        *(float4*)&sC[tt][n4] =
            *(const float4*)&g_xc[rowbase + (size_t)(c * CHUNK + tt) * CONVDIM
                                  + DINNER + DSTATE + n4];
    }
    if (tid < CHUNK)
        sa[tid] = g_acum[(b * SEQ + c * CHUNK + tid) * NHEADS + hh];
    __syncthreads();

#pragma unroll
    for (int it = 0; it < 4; it++) {
        int o  = tid + it * 256;
        int tt = o >> 4, p4 = (o & 15) * 4;
        float4 acc = make_float4(0.f, 0.f, 0.f, 0.f);
#pragma unroll 8
        for (int n = 0; n < DSTATE; n++) {
            float  cv = sC[tt][n];
            float4 hv = *(const float4*)&sHt[n][p4];
            acc.x = fmaf(cv, hv.x, acc.x);
            acc.y = fmaf(cv, hv.y, acc.y);
            acc.z = fmaf(cv, hv.z, acc.z);
            acc.w = fmaf(cv, hv.w, acc.w);
        }
        float at = sa[tt];
        size_t yi = (size_t)(b * SEQ + c * CHUNK + tt) * DINNER + hh * HEADDIM + p4;
        float4 y = *(float4*)&g_y[yi];
        y.x = fmaf(at, acc.x, y.x);
        y.y = fmaf(at, acc.y, y.y);
        y.z = fmaf(at, acc.z, y.z);
        y.w = fmaf(at, acc.w, y.w);
        *(float4*)&g_y[yi] = y;
    }
}

// ---------------- gate (silu(z)) + RMSNorm (writes tf32-rounded) ----------
__global__ void __launch_bounds__(256)
gate_norm_kernel(const float* __restrict__ norm_w)
{
    const int t = blockIdx.x;
    __shared__ float sg[DINNER];
    __shared__ float ssum[8];

    float local = 0.0f;
    for (int i = threadIdx.x; i < DINNER; i += 256) {
        float z = g_zx[(size_t)t * EPROJ + i];
        float g = g_y[(size_t)t * DINNER + i] * siluf(z);
        sg[i] = g;
        local = fmaf(g, g, local);
    }
#pragma unroll
    for (int off = 16; off; off >>= 1)
        local += __shfl_xor_sync(0xffffffffu, local, off);
    if ((threadIdx.x & 31) == 0) ssum[threadIdx.x >> 5] = local;
    __syncthreads();
    if (threadIdx.x < 8) {
        float v = ssum[threadIdx.x];
#pragma unroll
        for (int off = 4; off; off >>= 1)
            v += __shfl_xor_sync(0xffu, v, off);
        if (threadIdx.x == 0) ssum[0] = v;
    }
    __syncthreads();
    float scale = rsqrtf(ssum[0] / (float)DINNER + RMS_EPS);
    for (int i = threadIdx.x; i < DINNER; i += 256)
        g_nrm[(size_t)t * DINNER + i] = tf32r(sg[i] * scale * norm_w[i]);
}

// ---------------- decoders ----------------
__global__ void __launch_bounds__(128)
dec_cur_kernel(const float* __restrict__ w, const float* __restrict__ bias,
               float* __restrict__ out)
{
    int o = blockIdx.x * 4 + (threadIdx.x >> 5);   // 0..3071
    int lane = threadIdx.x & 31;
    int tok = o / VNUM, v = o % VNUM;
    const float* hr = &g_h[(size_t)tok * DMODEL];
    const float* wr = &w[v * DMODEL];
    float acc = 0.0f;
    for (int d = lane; d < DMODEL; d += 32) acc = fmaf(hr[d], wr[d], acc);
#pragma unroll
    for (int off = 16; off; off >>= 1)
        acc += __shfl_xor_sync(0xffffffffu, acc, off);
    if (lane == 0) out[o] = acc + bias[v];
}

__global__ void __launch_bounds__(128)
dec_fut_kernel(const float* __restrict__ w, const float* __restrict__ bias,
               float* __restrict__ out)
{
    int o = blockIdx.x * 4 + (threadIdx.x >> 5);   // 0..119
    int lane = threadIdx.x & 31;
    int b = o / (HORIZON * VNUM), j = o % (HORIZON * VNUM);
    const float* hr = &g_h[(size_t)(b * SEQ + (SEQ - 1)) * DMODEL];
    const float* wr = &w[j * DMODEL];
    float acc = 0.0f;
    for (int d = lane; d < DMODEL; d += 32) acc = fmaf(hr[d], wr[d], acc);
#pragma unroll
    for (int off = 16; off; off >>= 1)
        acc += __shfl_xor_sync(0xffffffffu, acc, off);
    if (lane == 0) out[BATCH * SEQ * VNUM + o] = acc + bias[j];
}

// ---------------- launch ----------------
extern "C" void kernel_launch(void* const* d_in, const int* in_sizes, int n_in,
                              void* d_out, int out_size)
{
    const float* embed      = (const float*)d_in[0];
    const float* in_proj_w  = (const float*)d_in[1];
    const float* conv_w     = (const float*)d_in[2];
    const float* conv_b     = (const float*)d_in[3];
    const float* dt_bias    = (const float*)d_in[4];
    const float* A_log      = (const float*)d_in[5];
    const float* Dp         = (const float*)d_in[6];
    const float* norm_w     = (const float*)d_in[7];
    const float* out_proj_w = (const float*)d_in[8];
    const float* dec_cur_w  = (const float*)d_in[9];
    const float* dec_cur_b  = (const float*)d_in[10];
    const float* dec_fut_w  = (const float*)d_in[11];
    const float* dec_fut_b  = (const float*)d_in[12];
    float* out = (float*)d_out;

    float *zx, *nrm, *h, *rA, *rW1, *rW2;
    cudaGetSymbolAddress((void**)&zx,  g_zx);
    cudaGetSymbolAddress((void**)&nrm, g_nrm);
    cudaGetSymbolAddress((void**)&h,   g_h);
    cudaGetSymbolAddress((void**)&rA,  g_rA);
    cudaGetSymbolAddress((void**)&rW1, g_rW1);
    cudaGetSymbolAddress((void**)&rW2, g_rW2);

    cudaFuncSetAttribute(gemm_tf32, cudaFuncAttributeMaxDynamicSharedMemorySize,
                         GEMM_SMEM_BYTES);

    // 0) pre-round GEMM operands to tf32 (hoists cvt out of mma inner loops)
    round_tf32_kernel<<<(NTOK * DMODEL / 4 + 255) / 256, 256>>>(embed, rA, NTOK * DMODEL / 4);
    round_tf32_kernel<<<(EPROJ * DMODEL / 4 + 255) / 256, 256>>>(in_proj_w, rW1, EPROJ * DMODEL / 4);
    round_tf32_kernel<<<(DMODEL * DINNER / 4 + 255) / 256, 256>>>(out_proj_w, rW2, DMODEL * DINNER / 4);

    // 1) in_proj: [1024,1024] x [4256,1024]^T -> [1024,4256]
    {
        dim3 grid((EPROJ + TBN - 1) / TBN, NTOK / TBM);   // 67 x 8
        gemm_tf32<<<grid, 256, GEMM_SMEM_BYTES>>>(rA, rW1, zx, NTOK, EPROJ, DMODEL);
    }
    // 2) causal conv + silu
    conv_silu_kernel<<<(NTOK * CONVDIM + 255) / 256, 256>>>(conv_w, conv_b);
    // 3) dt / la / dA
    dt_kernel<<<(NTOK * NHEADS + 255) / 256, 256>>>(dt_bias, A_log);
    // 3b) within-chunk cumulative dA (warp log-scan)
    acum_kernel<<<64, 256>>>();
    // 4a) intra-chunk scan
    {
        dim3 grid(4, NCHUNK, BATCH * NHEADS);
        scan_chunk_kernel<<<grid, 128>>>(Dp);
    }
    // 4b) inter-chunk state scan
    state_scan_kernel<<<(BATCH * NHEADS * HEADDIM * DSTATE) / 256, 256>>>();
    // 4c) correction
    {
        dim3 grid(NCHUNK - 1, BATCH * NHEADS);
        scan_correction_kernel<<<grid, 256>>>();
    }
    // 5) gate + rmsnorm (output tf32-rounded for the next GEMM)
    gate_norm_kernel<<<NTOK, 256>>>(norm_w);
    // 6) out_proj: [1024,2048] x [1024,2048]^T -> [1024,1024]
    {
        dim3 grid(DMODEL / TBN, NTOK / TBM);              // 16 x 8
        gemm_tf32<<<grid, 256, GEMM_SMEM_BYTES>>>(nrm, rW2, h, NTOK, DMODEL, DINNER);
    }
    // 7) decoders
    dec_cur_kernel<<<(NTOK * VNUM) / 4, 128>>>(dec_cur_w, dec_cur_b, out);
    dec_fut_kernel<<<(BATCH * HORIZON * VNUM) / 4, 128>>>(dec_fut_w, dec_fut_b, out);
}

// round 13
// speedup vs baseline: 1.5162x; 1.0488x over previous
#include <cuda_runtime.h>
#include <math.h>
#include <stdint.h>

// ---------------- problem constants ----------------
#define BATCH   2
#define SEQ     512
#define NTOK    (BATCH*SEQ)          // 1024
#define DMODEL  1024
#define DINNER  2048
#define DSTATE  64
#define HEADDIM 64
#define NHEADS  32
#define CONVDIM (DINNER + 2*DSTATE)  // 2176
#define EPROJ   (2*DINNER + 2*DSTATE + NHEADS) // 4256
#define DCONV   4
#define VNUM    3
#define HORIZON 20
#define RMS_EPS 1e-5f
#define CHUNK   64
#define NCHUNK  (SEQ/CHUNK)          // 8

// ---------------- device scratch (no cudaMalloc allowed) ----------------
__device__ float g_zx    [NTOK * EPROJ];    // in_proj output
__device__ float g_xc    [NTOK * CONVDIM];  // conv+silu output
__device__ float g_dt    [NTOK * NHEADS];   // softplus(dt)
__device__ float g_la    [NTOK * NHEADS];   // dt * A  (log of dA)
__device__ float g_dA    [NTOK * NHEADS];   // exp(dt*A)
__device__ float g_acum  [NTOK * NHEADS];   // within-chunk cumprod of dA
__device__ float g_state [BATCH*NHEADS*NCHUNK*HEADDIM*DSTATE]; // chunk-local end states
__device__ float g_hstart[BATCH*NHEADS*NCHUNK*HEADDIM*DSTATE]; // state at chunk start
__device__ float g_y     [NTOK * DINNER];   // scan output + D*x
__device__ float g_nrm   [NTOK * DINNER];   // gated+normed, tf32-rounded, K-PERMUTED
__device__ float g_h     [NTOK * DMODEL];   // out_proj output
// tf32-rounded + K-permuted GEMM operands ([k0,k4,k1,k5,k2,k6,k3,k7] per 8-group)
__device__ float g_rA    [NTOK * DMODEL];
__device__ float g_rW1   [EPROJ * DMODEL];
__device__ float g_rW2   [DMODEL * DINNER];

__device__ __forceinline__ float siluf(float x) { return x / (1.0f + expf(-x)); }
__device__ __forceinline__ float softplusf(float x) {
    return (x > 20.0f) ? x : log1pf(expf(x));
}
__device__ __forceinline__ float tf32r(float f) {
    uint32_t u;
    asm("cvt.rna.tf32.f32 %0, %1;\n" : "=r"(u) : "f"(f));
    return __uint_as_float(u);
}

// ---------------- cp.async helpers ----------------
__device__ __forceinline__ void cp_async16(void* smem, const void* gmem) {
    unsigned saddr = (unsigned)__cvta_generic_to_shared(smem);
    asm volatile("cp.async.cg.shared.global [%0], [%1], 16;\n" :: "r"(saddr), "l"(gmem));
}
__device__ __forceinline__ void cp_commit() {
    asm volatile("cp.async.commit_group;\n");
}
template <int N>
__device__ __forceinline__ void cp_wait() {
    asm volatile("cp.async.wait_group %0;\n" :: "n"(N));
}

// ---------------- tf32 round + K-permute pass ----------------
// Per 8-col k-group, output order [k0,k4,k1,k5,k2,k6,k3,k7].
__global__ void __launch_bounds__(256)
round_perm_kernel(const float* __restrict__ in, float* __restrict__ out, int n8)
{
    int i = blockIdx.x * 256 + threadIdx.x;
    if (i >= n8) return;
    float4 v0 = *(const float4*)&in[i * 8];
    float4 v1 = *(const float4*)&in[i * 8 + 4];
    float4 o0 = make_float4(tf32r(v0.x), tf32r(v1.x), tf32r(v0.y), tf32r(v1.y));
    float4 o1 = make_float4(tf32r(v0.z), tf32r(v1.z), tf32r(v0.w), tf32r(v1.w));
    *(float4*)&out[i * 8]     = o0;
    *(float4*)&out[i * 8 + 4] = o1;
}

// ---------------- tf32 raw-mma GEMM NT (3-stage ring, LDS.64 fragments) ---
// C[M,N] = A[M,K] * B[N,K]^T. Operands pre-rounded AND K-permuted.
// BM=128, BN=64, BK=32; 256 threads = 8 warps (4m x 2n), warp tile 32x32.
// TLD=40 (== 8 mod 32) -> all float2 fragment loads are bank-conflict-free.
#define TBM 128
#define TBN 64
#define TBK 32
#define TLD 40
#define STAGES 3
#define AS_STRIDE (TBM*TLD)              // 5120 floats / stage
#define BS_STRIDE (TBN*TLD)              // 2560 floats / stage
#define GEMM_SMEM_BYTES (STAGES*(AS_STRIDE+BS_STRIDE)*4)   // 92160 B

__device__ __forceinline__ void mma_tf32(float4& d,
                                         const uint32_t a0, const uint32_t a1,
                                         const uint32_t a2, const uint32_t a3,
                                         const uint32_t b0, const uint32_t b1) {
    asm volatile(
        "mma.sync.aligned.m16n8k8.row.col.f32.tf32.tf32.f32 "
        "{%0,%1,%2,%3}, {%4,%5,%6,%7}, {%8,%9}, {%0,%1,%2,%3};\n"
        : "+f"(d.x), "+f"(d.y), "+f"(d.z), "+f"(d.w)
        : "r"(a0), "r"(a1), "r"(a2), "r"(a3), "r"(b0), "r"(b1));
}

__global__ void __launch_bounds__(256, 2)
gemm_tf32(const float* __restrict__ A, const float* __restrict__ B,
          float* __restrict__ C, int M, int N, int K)
{
    extern __shared__ __align__(16) float smem[];
    float* As = smem;                         // [STAGES][TBM][TLD]
    float* Bs = smem + STAGES * AS_STRIDE;    // [STAGES][TBN][TLD]

    const int tid  = threadIdx.x;
    const int lane = tid & 31;
    const int warp = tid >> 5;
    const int wm   = (warp & 3) * 32;    // 4 warps over M
    const int wn   = (warp >> 2) * 32;   // 2 warps over N
    const int m0   = blockIdx.y * TBM;
    const int n0   = blockIdx.x * TBN;

    float4 acc[2][4];
#pragma unroll
    for (int i = 0; i < 2; i++)
#pragma unroll
        for (int j = 0; j < 4; j++) acc[i][j] = make_float4(0.f, 0.f, 0.f, 0.f);

    const int ntiles = K / TBK;

    auto issue_tile = [&](int kt, int stg) {
        const size_t ko = (size_t)kt * TBK;
        float* as = As + stg * AS_STRIDE;
        float* bs = Bs + stg * BS_STRIDE;
#pragma unroll
        for (int k = 0; k < 4; k++) {            // 1024 float4 slots for A
            int slot = tid + k * 256;
            int r = slot >> 3, c = (slot & 7) * 4;
            cp_async16(&as[r * TLD + c], A + (size_t)(m0 + r) * K + ko + c);
        }
#pragma unroll
        for (int k = 0; k < 2; k++) {            // 512 float4 slots for B
            int slot = tid + k * 256;
            int r = slot >> 3, c = (slot & 7) * 4;
            int rr = (n0 + r < N) ? (n0 + r) : (N - 1);   // clamp; masked at store
            cp_async16(&bs[r * TLD + c], B + (size_t)rr * K + ko + c);
        }
        cp_commit();
    };

    issue_tile(0, 0);
    if (ntiles > 1) issue_tile(1, 1);

    const int lr = lane >> 2;       // 0..7
    const int lc = lane & 3;        // 0..3

    for (int kt = 0; kt < ntiles; kt++) {
        if (kt + 1 == ntiles) cp_wait<0>(); else cp_wait<1>();
        __syncthreads();
        if (kt + STAGES - 1 < ntiles)
            issue_tile(kt + STAGES - 1, (kt + STAGES - 1) % STAGES);

        const float* Asb = As + (kt % STAGES) * AS_STRIDE;
        const float* Bsb = Bs + (kt % STAGES) * BS_STRIDE;

#pragma unroll
        for (int ks = 0; ks < TBK / 8; ks++) {
            const int kb = ks * 8 + 2 * lc;     // permuted: (lc, lc+4) adjacent
            uint32_t af[2][4];
#pragma unroll
            for (int i = 0; i < 2; i++) {
                const float* ap = Asb + (size_t)(wm + i * 16 + lr) * TLD + kb;
                float2 u0 = *(const float2*)ap;              // a0 (lc), a2 (lc+4)
                float2 u1 = *(const float2*)(ap + 8 * TLD);  // a1, a3
                af[i][0] = __float_as_uint(u0.x);
                af[i][1] = __float_as_uint(u1.x);
                af[i][2] = __float_as_uint(u0.y);
                af[i][3] = __float_as_uint(u1.y);
            }
            uint32_t bf[4][2];
#pragma unroll
            for (int j = 0; j < 4; j++) {
                float2 v = *(const float2*)(Bsb + (size_t)(wn + j * 8 + lr) * TLD + kb);
                bf[j][0] = __float_as_uint(v.x);
                bf[j][1] = __float_as_uint(v.y);
            }
#pragma unroll
            for (int i = 0; i < 2; i++)
#pragma unroll
                for (int j = 0; j < 4; j++)
                    mma_tf32(acc[i][j], af[i][0], af[i][1], af[i][2], af[i][3],
                             bf[j][0], bf[j][1]);
        }
    }

#pragma unroll
    for (int i = 0; i < 2; i++)
#pragma unroll
        for (int j = 0; j < 4; j++) {
            int r  = m0 + wm + i * 16 + lr;
            int cn = n0 + wn + j * 8 + lc * 2;
            if (cn < N) {
                *(float2*)&C[(size_t)r * N + cn] =
                    make_float2(acc[i][j].x, acc[i][j].y);
                *(float2*)&C[(size_t)(r + 8) * N + cn] =
                    make_float2(acc[i][j].z, acc[i][j].w);
            }
        }
}

// ---------------- fused conv+silu and dt/la/dA ----------------
__global__ void __launch_bounds__(256)
conv_dt_kernel(const float* __restrict__ conv_w, const float* __restrict__ conv_b,
               const float* __restrict__ dt_bias, const float* __restrict__ A_log)
{
    int idx = blockIdx.x * blockDim.x + threadIdx.x;
    if (idx < NTOK * CONVDIM) {
        int c = idx % CONVDIM;
        int t = idx / CONVDIM;
        int s = t & (SEQ - 1);
        int b = t >> 9;
        float acc = conv_b[c];
#pragma unroll
        for (int k = 0; k < DCONV; k++) {
            int ss = s + k - (DCONV - 1);
            if (ss >= 0)
                acc = fmaf(conv_w[c * DCONV + k],
                           g_zx[(size_t)(b * SEQ + ss) * EPROJ + DINNER + c], acc);
        }
        g_xc[(size_t)t * CONVDIM + c] = siluf(acc);
    } else {
        int j = idx - NTOK * CONVDIM;
        if (j >= NTOK * NHEADS) return;
        int hh = j & (NHEADS - 1);
        int t  = j >> 5;
        float raw = g_zx[(size_t)t * EPROJ + DINNER + CONVDIM + hh];
        float dtv = softplusf(raw + dt_bias[hh]);
        float Ah  = -expf(A_log[hh]);
        float la  = dtv * Ah;
        g_dt[j] = dtv;
        g_la[j] = la;
        g_dA[j] = expf(la);
    }
}

// ---------------- within-chunk cumulative dA via warp log-scan ------------
__global__ void __launch_bounds__(256)
acum_kernel()
{
    int w    = (blockIdx.x * 256 + threadIdx.x) >> 5;   // 0..511
    int lane = threadIdx.x & 31;
    if (w >= BATCH * NHEADS * NCHUNK) return;
    int chunk = w & (NCHUNK - 1);
    int hh    = (w >> 3) & (NHEADS - 1);
    int b     = w >> 8;
    int base  = (b * SEQ + chunk * CHUNK) * NHEADS + hh;

    float l0 = g_la[base + (lane * 2)     * NHEADS];
    float l1 = g_la[base + (lane * 2 + 1) * NHEADS];
    float loc = l0 + l1;
    float sc = loc;
#pragma unroll
    for (int off = 1; off < 32; off <<= 1) {
        float v = __shfl_up_sync(0xffffffffu, sc, off);
        if (lane >= off) sc += v;
    }
    float excl = sc - loc;
    g_acum[base + (lane * 2)     * NHEADS] = expf(excl + l0);
    g_acum[base + (lane * 2 + 1) * NHEADS] = expf(excl + loc);
}

// ---------------- pass 1: intra-chunk scan (zero initial state) ----------------
__global__ void __launch_bounds__(128)
scan_chunk_kernel(const float* __restrict__ Dp)
{
    const int bz = blockIdx.z;
    const int b  = bz >> 5;
    const int hh = bz & (NHEADS - 1);
    const int chunk = blockIdx.y;
    const int pb = blockIdx.x * 16;
    const int t  = threadIdx.x;
    const int lp = t >> 3;
    const int n0 = (t & 7) * 8;

    __shared__ __align__(16) float sB[32][64];
    __shared__ __align__(16) float sC[32][64];
    __shared__ __align__(16) float sX[32][16];
    __shared__ float sdA[32], sdt[32];

    float hst[8];
#pragma unroll
    for (int j = 0; j < 8; j++) hst[j] = 0.0f;

    const float Dh = Dp[hh];
    const size_t rowbase = (size_t)(b * SEQ) * CONVDIM;

#pragma unroll
    for (int sub = 0; sub < 2; sub++) {
        const int s0 = chunk * CHUNK + sub * 32;
        for (int i = t; i < 512; i += 128) {
            int si = i >> 4, j4 = (i & 15) * 4;
            size_t r = rowbase + (size_t)(s0 + si) * CONVDIM;
            *(float4*)&sB[si][j4] = *(const float4*)&g_xc[r + DINNER + j4];
            *(float4*)&sC[si][j4] = *(const float4*)&g_xc[r + DINNER + DSTATE + j4];
        }
        {
            int si = t >> 2, j4 = (t & 3) * 4;
            size_t r = rowbase + (size_t)(s0 + si) * CONVDIM;
            *(float4*)&sX[si][j4] = *(const float4*)&g_xc[r + hh * HEADDIM + pb + j4];
        }
        if (t < 32) {
            int idx = (b * SEQ + s0 + t) * NHEADS + hh;
            sdA[t] = g_dA[idx];
            sdt[t] = g_dt[idx];
        }
        __syncthreads();

        for (int si = 0; si < 32; si++) {
            float dAv = sdA[si];
            float xv  = sX[si][lp];
            float dtx = sdt[si] * xv;
            float4 b0 = *(const float4*)&sB[si][n0];
            float4 b1 = *(const float4*)&sB[si][n0 + 4];
            float4 c0 = *(const float4*)&sC[si][n0];
            float4 c1 = *(const float4*)&sC[si][n0 + 4];
            float yp;
            hst[0] = fmaf(hst[0], dAv, dtx * b0.x); yp  = hst[0] * c0.x;
            hst[1] = fmaf(hst[1], dAv, dtx * b0.y); yp += hst[1] * c0.y;
            hst[2] = fmaf(hst[2], dAv, dtx * b0.z); yp += hst[2] * c0.z;
            hst[3] = fmaf(hst[3], dAv, dtx * b0.w); yp += hst[3] * c0.w;
            hst[4] = fmaf(hst[4], dAv, dtx * b1.x); yp += hst[4] * c1.x;
            hst[5] = fmaf(hst[5], dAv, dtx * b1.y); yp += hst[5] * c1.y;
            hst[6] = fmaf(hst[6], dAv, dtx * b1.z); yp += hst[6] * c1.z;
            hst[7] = fmaf(hst[7], dAv, dtx * b1.w); yp += hst[7] * c1.w;
            yp += __shfl_xor_sync(0xffffffffu, yp, 1);
            yp += __shfl_xor_sync(0xffffffffu, yp, 2);
            yp += __shfl_xor_sync(0xffffffffu, yp, 4);
            if ((t & 7) == 0)
                g_y[(size_t)(b * SEQ + s0 + si) * DINNER + hh * HEADDIM + pb + lp] =
                    yp + Dh * xv;
        }
        __syncthreads();
    }

    size_t st = (((size_t)bz * NCHUNK + chunk) * HEADDIM + (pb + lp)) * DSTATE + n0;
    *(float4*)&g_state[st]     = make_float4(hst[0], hst[1], hst[2], hst[3]);
    *(float4*)&g_state[st + 4] = make_float4(hst[4], hst[5], hst[6], hst[7]);
}

// ---------------- pass 2: inter-chunk state scan ----------------
__global__ void __launch_bounds__(256)
state_scan_kernel()
{
    int idx = blockIdx.x * 256 + threadIdx.x;
    int n  = idx & 63;
    int p  = (idx >> 6) & 63;
    int bz = idx >> 12;
    int b  = bz >> 5, hh = bz & (NHEADS - 1);
    size_t base = (size_t)bz * (NCHUNK * HEADDIM * DSTATE) + (size_t)p * DSTATE + n;
    float hs = 0.0f;
#pragma unroll
    for (int c = 1; c < NCHUNK; c++) {
        float P = g_acum[((b * SEQ) + (c - 1) * CHUNK + (CHUNK - 1)) * NHEADS + hh];
        hs = fmaf(P, hs, g_state[base + (size_t)(c - 1) * (HEADDIM * DSTATE)]);
        g_hstart[base + (size_t)c * (HEADDIM * DSTATE)] = hs;
    }
}

// ---------------- pass 3: correction  y[t] += a(t) * (C[t] . h_start) ------
__global__ void __launch_bounds__(256)
scan_correction_kernel()
{
    const int c  = blockIdx.x + 1;        // chunks 1..7
    const int bz = blockIdx.y;
    const int b  = bz >> 5, hh = bz & (NHEADS - 1);
    const int tid = threadIdx.x;

    __shared__ __align__(16) float sHt[DSTATE][HEADDIM + 4];
    __shared__ __align__(16) float sC [CHUNK][DSTATE];
    __shared__ float sa[CHUNK];

    size_t hb = (size_t)bz * (NCHUNK * HEADDIM * DSTATE) + (size_t)c * (HEADDIM * DSTATE);
#pragma unroll
    for (int k = 0; k < 4; k++) {
        int i = tid + k * 256;
        int p = i >> 4, n4 = (i & 15) * 4;
        float4 v = *(const float4*)&g_hstart[hb + (size_t)p * DSTATE + n4];
        sHt[n4 + 0][p] = v.x; sHt[n4 + 1][p] = v.y;
        sHt[n4 + 2][p] = v.z; sHt[n4 + 3][p] = v.w;
    }
    const size_t rowbase = (size_t)(b * SEQ) * CONVDIM;
#pragma unroll
    for (int k = 0; k < 4; k++) {
        int i = tid + k * 256;
        int tt = i >> 4, n4 = (i & 15) * 4;
        *(float4*)&sC[tt][n4] =
            *(const float4*)&g_xc[rowbase + (size_t)(c * CHUNK + tt) * CONVDIM
                                  + DINNER + DSTATE + n4];
    }
    if (tid < CHUNK)
        sa[tid] = g_acum[(b * SEQ + c * CHUNK + tid) * NHEADS + hh];
    __syncthreads();

#pragma unroll
    for (int it = 0; it < 4; it++) {
        int o  = tid + it * 256;
        int tt = o >> 4, p4 = (o & 15) * 4;
        float4 acc = make_float4(0.f, 0.f, 0.f, 0.f);
#pragma unroll 8
        for (int n = 0; n < DSTATE; n++) {
            float  cv = sC[tt][n];
            float4 hv = *(const float4*)&sHt[n][p4];
            acc.x = fmaf(cv, hv.x, acc.x);
            acc.y = fmaf(cv, hv.y, acc.y);
            acc.z = fmaf(cv, hv.z, acc.z);
            acc.w = fmaf(cv, hv.w, acc.w);
        }
        float at = sa[tt];
        size_t yi = (size_t)(b * SEQ + c * CHUNK + tt) * DINNER + hh * HEADDIM + p4;
        float4 y = *(float4*)&g_y[yi];
        y.x = fmaf(at, acc.x, y.x);
        y.y = fmaf(at, acc.y, y.y);
        y.z = fmaf(at, acc.z, y.z);
        y.w = fmaf(at, acc.w, y.w);
        *(float4*)&g_y[yi] = y;
    }
}

// ---------------- gate + RMSNorm (writes tf32-rounded, K-PERMUTED) --------
__global__ void __launch_bounds__(256)
gate_norm_kernel(const float* __restrict__ norm_w)
{
    const int t = blockIdx.x;
    __shared__ float sg[DINNER];
    __shared__ float ssum[8];

    float local = 0.0f;
    for (int i = threadIdx.x; i < DINNER; i += 256) {
        float z = g_zx[(size_t)t * EPROJ + i];
        float g = g_y[(size_t)t * DINNER + i] * siluf(z);
        sg[i] = g;
        local = fmaf(g, g, local);
    }
#pragma unroll
    for (int off = 16; off; off >>= 1)
        local += __shfl_xor_sync(0xffffffffu, local, off);
    if ((threadIdx.x & 31) == 0) ssum[threadIdx.x >> 5] = local;
    __syncthreads();
    if (threadIdx.x < 8) {
        float v = ssum[threadIdx.x];
#pragma unroll
        for (int off = 4; off; off >>= 1)
            v += __shfl_xor_sync(0xffu, v, off);
        if (threadIdx.x == 0) ssum[0] = v;
    }
    __syncthreads();
    float scale = rsqrtf(ssum[0] / (float)DINNER + RMS_EPS);
    for (int i = threadIdx.x; i < DINNER; i += 256) {
        // permute within 8-group: l<4 -> 2l ; l>=4 -> 2(l-4)+1
        int p   = 2 * (i & 3) + ((i & 4) ? 1 : 0);
        int idx = (i & ~7) | p;
        g_nrm[(size_t)t * DINNER + idx] = tf32r(sg[i] * scale * norm_w[i]);
    }
}

// ---------------- merged decoders ----------------
__global__ void __launch_bounds__(128)
dec_kernel(const float* __restrict__ cw, const float* __restrict__ cb,
           const float* __restrict__ fw, const float* __restrict__ fb,
           float* __restrict__ out)
{
    int o = blockIdx.x * 4 + (threadIdx.x >> 5);
    int lane = threadIdx.x & 31;
    const float* hr;
    const float* wr;
    float bias;
    int oi;
    if (o < NTOK * VNUM) {
        int tok = o / VNUM, v = o % VNUM;
        hr = &g_h[(size_t)tok * DMODEL];
        wr = &cw[v * DMODEL];
        bias = cb[v];
        oi = o;
    } else {
        int o2 = o - NTOK * VNUM;
        if (o2 >= BATCH * HORIZON * VNUM) return;
        int b = o2 / (HORIZON * VNUM), j = o2 % (HORIZON * VNUM);
        hr = &g_h[(size_t)(b * SEQ + (SEQ - 1)) * DMODEL];
        wr = &fw[j * DMODEL];
        bias = fb[j];
        oi = NTOK * VNUM + o2;
    }
    float acc = 0.0f;
    for (int d = lane; d < DMODEL; d += 32) acc = fmaf(hr[d], wr[d], acc);
#pragma unroll
    for (int off = 16; off; off >>= 1)
        acc += __shfl_xor_sync(0xffffffffu, acc, off);
    if (lane == 0) out[oi] = acc + bias;
}

// ---------------- launch ----------------
extern "C" void kernel_launch(void* const* d_in, const int* in_sizes, int n_in,
                              void* d_out, int out_size)
{
    const float* embed      = (const float*)d_in[0];
    const float* in_proj_w  = (const float*)d_in[1];
    const float* conv_w     = (const float*)d_in[2];
    const float* conv_b     = (const float*)d_in[3];
    const float* dt_bias    = (const float*)d_in[4];
    const float* A_log      = (const float*)d_in[5];
    const float* Dp         = (const float*)d_in[6];
    const float* norm_w     = (const float*)d_in[7];
    const float* out_proj_w = (const float*)d_in[8];
    const float* dec_cur_w  = (const float*)d_in[9];
    const float* dec_cur_b  = (const float*)d_in[10];
    const float* dec_fut_w  = (const float*)d_in[11];
    const float* dec_fut_b  = (const float*)d_in[12];
    float* out = (float*)d_out;

    float *zx, *nrm, *h, *rA, *rW1, *rW2;
    cudaGetSymbolAddress((void**)&zx,  g_zx);
    cudaGetSymbolAddress((void**)&nrm, g_nrm);
    cudaGetSymbolAddress((void**)&h,   g_h);
    cudaGetSymbolAddress((void**)&rA,  g_rA);
    cudaGetSymbolAddress((void**)&rW1, g_rW1);
    cudaGetSymbolAddress((void**)&rW2, g_rW2);

    cudaFuncSetAttribute(gemm_tf32, cudaFuncAttributeMaxDynamicSharedMemorySize,
                         GEMM_SMEM_BYTES);

    // 0) round + K-permute GEMM operands
    round_perm_kernel<<<(NTOK * DMODEL / 8 + 255) / 256, 256>>>(embed, rA, NTOK * DMODEL / 8);
    round_perm_kernel<<<(EPROJ * DMODEL / 8 + 255) / 256, 256>>>(in_proj_w, rW1, EPROJ * DMODEL / 8);
    round_perm_kernel<<<(DMODEL * DINNER / 8 + 255) / 256, 256>>>(out_proj_w, rW2, DMODEL * DINNER / 8);

    // 1) in_proj: [1024,1024] x [4256,1024]^T -> [1024,4256]
    {
        dim3 grid((EPROJ + TBN - 1) / TBN, NTOK / TBM);   // 67 x 8
        gemm_tf32<<<grid, 256, GEMM_SMEM_BYTES>>>(rA, rW1, zx, NTOK, EPROJ, DMODEL);
    }
    // 2) fused conv+silu and dt/la/dA
    conv_dt_kernel<<<(NTOK * (CONVDIM + NHEADS) + 255) / 256, 256>>>(conv_w, conv_b,
                                                                     dt_bias, A_log);
    // 3) within-chunk cumulative dA (warp log-scan)
    acum_kernel<<<64, 256>>>();
    // 4a) intra-chunk scan
    {
        dim3 grid(4, NCHUNK, BATCH * NHEADS);
        scan_chunk_kernel<<<grid, 128>>>(Dp);
    }
    // 4b) inter-chunk state scan
    state_scan_kernel<<<(BATCH * NHEADS * HEADDIM * DSTATE) / 256, 256>>>();
    // 4c) correction
    {
        dim3 grid(NCHUNK - 1, BATCH * NHEADS);
        scan_correction_kernel<<<grid, 256>>>();
    }
    // 5) gate + rmsnorm (tf32-rounded + permuted for out_proj)
    gate_norm_kernel<<<NTOK, 256>>>(norm_w);
    // 6) out_proj: [1024,2048] x [1024,2048]^T -> [1024,1024]
    {
        dim3 grid(DMODEL / TBN, NTOK / TBM);              // 16 x 8
        gemm_tf32<<<grid, 256, GEMM_SMEM_BYTES>>>(nrm, rW2, h, NTOK, DMODEL, DINNER);
    }
    // 7) merged decoders
    dec_kernel<<<(NTOK * VNUM + BATCH * HORIZON * VNUM + 3) / 4, 128>>>(
        dec_cur_w, dec_cur_b, dec_fut_w, dec_fut_b, out);
}

// round 16
// speedup vs baseline: 1.5643x; 1.0317x over previous
#include <cuda_runtime.h>
#include <math.h>
#include <stdint.h>

// ---------------- problem constants ----------------
#define BATCH   2
#define SEQ     512
#define NTOK    (BATCH*SEQ)          // 1024
#define DMODEL  1024
#define DINNER  2048
#define DSTATE  64
#define HEADDIM 64
#define NHEADS  32
#define CONVDIM (DINNER + 2*DSTATE)  // 2176
#define EPROJ   (2*DINNER + 2*DSTATE + NHEADS) // 4256
#define DCONV   4
#define VNUM    3
#define HORIZON 20
#define RMS_EPS 1e-5f
#define CHUNK   64
#define NCHUNK  (SEQ/CHUNK)          // 8

// ---------------- device scratch (no cudaMalloc allowed) ----------------
__device__ float g_zx    [NTOK * EPROJ];    // in_proj output
__device__ float g_xc    [NTOK * CONVDIM];  // conv+silu output
__device__ float g_dt    [NTOK * NHEADS];   // softplus(dt)
__device__ float g_la    [NTOK * NHEADS];   // dt * A  (log of dA)
__device__ float g_dA    [NTOK * NHEADS];   // exp(dt*A)
__device__ float g_acum  [NTOK * NHEADS];   // within-chunk cumprod of dA
__device__ float g_state [BATCH*NHEADS*NCHUNK*HEADDIM*DSTATE]; // chunk-local end states
__device__ float g_hstart[BATCH*NHEADS*NCHUNK*HEADDIM*DSTATE]; // state at chunk start
__device__ float g_y     [NTOK * DINNER];   // scan output + D*x
__device__ float g_nrm   [NTOK * DINNER];   // gated+normed, tf32-rounded, K-PERMUTED
__device__ float g_h     [NTOK * DMODEL];   // out_proj output
// tf32-rounded + K-permuted GEMM operands ([k0,k4,k1,k5,k2,k6,k3,k7] per 8-group)
__device__ float g_rA    [NTOK * DMODEL];
__device__ float g_rW1   [EPROJ * DMODEL];
__device__ float g_rW2   [DMODEL * DINNER];

__device__ __forceinline__ float siluf(float x) { return x / (1.0f + expf(-x)); }
__device__ __forceinline__ float softplusf(float x) {
    return (x > 20.0f) ? x : log1pf(expf(x));
}
__device__ __forceinline__ float tf32r(float f) {
    uint32_t u;
    asm("cvt.rna.tf32.f32 %0, %1;\n" : "=r"(u) : "f"(f));
    return __uint_as_float(u);
}

// ---------------- cp.async helpers ----------------
__device__ __forceinline__ void cp_async16(void* smem, const void* gmem) {
    unsigned saddr = (unsigned)__cvta_generic_to_shared(smem);
    asm volatile("cp.async.cg.shared.global [%0], [%1], 16;\n" :: "r"(saddr), "l"(gmem));
}
__device__ __forceinline__ void cp_commit() {
    asm volatile("cp.async.commit_group;\n");
}
template <int N>
__device__ __forceinline__ void cp_wait() {
    asm volatile("cp.async.wait_group %0;\n" :: "n"(N));
}

// ---------------- fused tf32 round + K-permute for all 3 operands ---------
// Per 8-col k-group, output order [k0,k4,k1,k5,k2,k6,k3,k7].
#define N8_A  (NTOK * DMODEL / 8)      // 131072
#define N8_W1 (EPROJ * DMODEL / 8)     // 544768
#define N8_W2 (DMODEL * DINNER / 8)    // 262144

__global__ void __launch_bounds__(256)
round_perm_all(const float* __restrict__ inA, const float* __restrict__ inW1,
               const float* __restrict__ inW2)
{
    int i = blockIdx.x * 256 + threadIdx.x;
    const float* in;
    float* out;
    if (i < N8_A)                { in = inA;  out = g_rA;  }
    else if (i < N8_A + N8_W1)   { in = inW1; out = g_rW1; i -= N8_A; }
    else if (i < N8_A + N8_W1 + N8_W2) { in = inW2; out = g_rW2; i -= N8_A + N8_W1; }
    else return;
    float4 v0 = *(const float4*)&in[i * 8];
    float4 v1 = *(const float4*)&in[i * 8 + 4];
    float4 o0 = make_float4(tf32r(v0.x), tf32r(v1.x), tf32r(v0.y), tf32r(v1.y));
    float4 o1 = make_float4(tf32r(v0.z), tf32r(v1.z), tf32r(v0.w), tf32r(v1.w));
    *(float4*)&out[i * 8]     = o0;
    *(float4*)&out[i * 8 + 4] = o1;
}

// ---------------- tf32 raw-mma GEMM NT (high-ILP warp tiles) --------------
// C[M,N] = A[M,K] * B[N,K]^T. Operands pre-rounded AND K-permuted.
// BM=128, BN=64, BK=32; 128 threads = 4 warps (2m x 2n), warp tile 64x32
// (4 m-frags x 4 n-frags = 16 mma per ks-step, 12 LDS.64).
// TLD=40 -> all float2 fragment loads are bank-conflict-free.
#define TBM 128
#define TBN 64
#define TBK 32
#define TLD 40
#define STAGES 3
#define AS_STRIDE (TBM*TLD)              // 5120 floats / stage
#define BS_STRIDE (TBN*TLD)              // 2560 floats / stage
#define GEMM_SMEM_BYTES (STAGES*(AS_STRIDE+BS_STRIDE)*4)   // 92160 B

__device__ __forceinline__ void mma_tf32(float4& d,
                                         const uint32_t a0, const uint32_t a1,
                                         const uint32_t a2, const uint32_t a3,
                                         const uint32_t b0, const uint32_t b1) {
    asm volatile(
        "mma.sync.aligned.m16n8k8.row.col.f32.tf32.tf32.f32 "
        "{%0,%1,%2,%3}, {%4,%5,%6,%7}, {%8,%9}, {%0,%1,%2,%3};\n"
        : "+f"(d.x), "+f"(d.y), "+f"(d.z), "+f"(d.w)
        : "r"(a0), "r"(a1), "r"(a2), "r"(a3), "r"(b0), "r"(b1));
}

__global__ void __launch_bounds__(128)
gemm_tf32(const float* __restrict__ A, const float* __restrict__ B,
          float* __restrict__ C, int M, int N, int K)
{
    extern __shared__ __align__(16) float smem[];
    float* As = smem;                         // [STAGES][TBM][TLD]
    float* Bs = smem + STAGES * AS_STRIDE;    // [STAGES][TBN][TLD]

    const int tid  = threadIdx.x;
    const int lane = tid & 31;
    const int warp = tid >> 5;
    const int wm   = (warp & 1) * 64;    // 2 warps over M, tile 64
    const int wn   = (warp >> 1) * 32;   // 2 warps over N, tile 32
    const int m0   = blockIdx.y * TBM;
    const int n0   = blockIdx.x * TBN;

    float4 acc[4][4];
#pragma unroll
    for (int i = 0; i < 4; i++)
#pragma unroll
        for (int j = 0; j < 4; j++) acc[i][j] = make_float4(0.f, 0.f, 0.f, 0.f);

    const int ntiles = K / TBK;

    auto issue_tile = [&](int kt, int stg) {
        const size_t ko = (size_t)kt * TBK;
        float* as = As + stg * AS_STRIDE;
        float* bs = Bs + stg * BS_STRIDE;
#pragma unroll
        for (int k = 0; k < 8; k++) {            // 1024 float4 slots for A
            int slot = tid + k * 128;
            int r = slot >> 3, c = (slot & 7) * 4;
            cp_async16(&as[r * TLD + c], A + (size_t)(m0 + r) * K + ko + c);
        }
#pragma unroll
        for (int k = 0; k < 4; k++) {            // 512 float4 slots for B
            int slot = tid + k * 128;
            int r = slot >> 3, c = (slot & 7) * 4;
            int rr = (n0 + r < N) ? (n0 + r) : (N - 1);   // clamp; masked at store
            cp_async16(&bs[r * TLD + c], B + (size_t)rr * K + ko + c);
        }
        cp_commit();
    };

    issue_tile(0, 0);
    if (ntiles > 1) issue_tile(1, 1);

    const int lr = lane >> 2;       // 0..7
    const int lc = lane & 3;        // 0..3

    for (int kt = 0; kt < ntiles; kt++) {
        if (kt + 1 == ntiles) cp_wait<0>(); else cp_wait<1>();
        __syncthreads();
        if (kt + STAGES - 1 < ntiles)
            issue_tile(kt + STAGES - 1, (kt + STAGES - 1) % STAGES);

        const float* Asw = As + (kt % STAGES) * AS_STRIDE + (size_t)(wm + lr) * TLD;
        const float* Bsw = Bs + (kt % STAGES) * BS_STRIDE + (size_t)(wn + lr) * TLD;

#pragma unroll
        for (int ks = 0; ks < TBK / 8; ks++) {
            const int kb = ks * 8 + 2 * lc;     // permuted: (lc, lc+4) adjacent
            uint32_t af[4][4];
#pragma unroll
            for (int i = 0; i < 4; i++) {
                const float* ap = Asw + i * 16 * TLD + kb;
                float2 u0 = *(const float2*)ap;              // rows lr / lr+8
                float2 u1 = *(const float2*)(ap + 8 * TLD);
                af[i][0] = __float_as_uint(u0.x);
                af[i][1] = __float_as_uint(u1.x);
                af[i][2] = __float_as_uint(u0.y);
                af[i][3] = __float_as_uint(u1.y);
            }
            uint32_t bf[4][2];
#pragma unroll
            for (int j = 0; j < 4; j++) {
                float2 v = *(const float2*)(Bsw + j * 8 * TLD + kb);
                bf[j][0] = __float_as_uint(v.x);
                bf[j][1] = __float_as_uint(v.y);
            }
#pragma unroll
            for (int i = 0; i < 4; i++)
#pragma unroll
                for (int j = 0; j < 4; j++)
                    mma_tf32(acc[i][j], af[i][0], af[i][1], af[i][2], af[i][3],
                             bf[j][0], bf[j][1]);
        }
    }

#pragma unroll
    for (int i = 0; i < 4; i++)
#pragma unroll
        for (int j = 0; j < 4; j++) {
            int r  = m0 + wm + i * 16 + lr;
            int cn = n0 + wn + j * 8 + lc * 2;
            if (cn < N) {
                *(float2*)&C[(size_t)r * N + cn] =
                    make_float2(acc[i][j].x, acc[i][j].y);
                *(float2*)&C[(size_t)(r + 8) * N + cn] =
                    make_float2(acc[i][j].z, acc[i][j].w);
            }
        }
}

// ---------------- fused conv+silu and dt/la/dA ----------------
__global__ void __launch_bounds__(256)
conv_dt_kernel(const float* __restrict__ conv_w, const float* __restrict__ conv_b,
               const float* __restrict__ dt_bias, const float* __restrict__ A_log)
{
    int idx = blockIdx.x * blockDim.x + threadIdx.x;
    if (idx < NTOK * CONVDIM) {
        int c = idx % CONVDIM;
        int t = idx / CONVDIM;
        int s = t & (SEQ - 1);
        int b = t >> 9;
        float acc = conv_b[c];
#pragma unroll
        for (int k = 0; k < DCONV; k++) {
            int ss = s + k - (DCONV - 1);
            if (ss >= 0)
                acc = fmaf(conv_w[c * DCONV + k],
                           g_zx[(size_t)(b * SEQ + ss) * EPROJ + DINNER + c], acc);
        }
        g_xc[(size_t)t * CONVDIM + c] = siluf(acc);
    } else {
        int j = idx - NTOK * CONVDIM;
        if (j >= NTOK * NHEADS) return;
        int hh = j & (NHEADS - 1);
        int t  = j >> 5;
        float raw = g_zx[(size_t)t * EPROJ + DINNER + CONVDIM + hh];
        float dtv = softplusf(raw + dt_bias[hh]);
        float Ah  = -expf(A_log[hh]);
        float la  = dtv * Ah;
        g_dt[j] = dtv;
        g_la[j] = la;
        g_dA[j] = expf(la);
    }
}

// ---------------- within-chunk cumulative dA via warp log-scan ------------
__global__ void __launch_bounds__(256)
acum_kernel()
{
    int w    = (blockIdx.x * 256 + threadIdx.x) >> 5;   // 0..511
    int lane = threadIdx.x & 31;
    if (w >= BATCH * NHEADS * NCHUNK) return;
    int chunk = w & (NCHUNK - 1);
    int hh    = (w >> 3) & (NHEADS - 1);
    int b     = w >> 8;
    int base  = (b * SEQ + chunk * CHUNK) * NHEADS + hh;

    float l0 = g_la[base + (lane * 2)     * NHEADS];
    float l1 = g_la[base + (lane * 2 + 1) * NHEADS];
    float loc = l0 + l1;
    float sc = loc;
#pragma unroll
    for (int off = 1; off < 32; off <<= 1) {
        float v = __shfl_up_sync(0xffffffffu, sc, off);
        if (lane >= off) sc += v;
    }
    float excl = sc - loc;
    g_acum[base + (lane * 2)     * NHEADS] = expf(excl + l0);
    g_acum[base + (lane * 2 + 1) * NHEADS] = expf(excl + loc);
}

// ---------------- pass 1: intra-chunk scan (zero initial state) ----------------
__global__ void __launch_bounds__(128)
scan_chunk_kernel(const float* __restrict__ Dp)
{
    const int bz = blockIdx.z;
    const int b  = bz >> 5;
    const int hh = bz & (NHEADS - 1);
    const int chunk = blockIdx.y;
    const int pb = blockIdx.x * 16;
    const int t  = threadIdx.x;
    const int lp = t >> 3;
    const int n0 = (t & 7) * 8;

    __shared__ __align__(16) float sB[32][64];
    __shared__ __align__(16) float sC[32][64];
    __shared__ __align__(16) float sX[32][16];
    __shared__ float sdA[32], sdt[32];

    float hst[8];
#pragma unroll
    for (int j = 0; j < 8; j++) hst[j] = 0.0f;

    const float Dh = Dp[hh];
    const size_t rowbase = (size_t)(b * SEQ) * CONVDIM;

#pragma unroll
    for (int sub = 0; sub < 2; sub++) {
        const int s0 = chunk * CHUNK + sub * 32;
        for (int i = t; i < 512; i += 128) {
            int si = i >> 4, j4 = (i & 15) * 4;
            size_t r = rowbase + (size_t)(s0 + si) * CONVDIM;
            *(float4*)&sB[si][j4] = *(const float4*)&g_xc[r + DINNER + j4];
            *(float4*)&sC[si][j4] = *(const float4*)&g_xc[r + DINNER + DSTATE + j4];
        }
        {
            int si = t >> 2, j4 = (t & 3) * 4;
            size_t r = rowbase + (size_t)(s0 + si) * CONVDIM;
            *(float4*)&sX[si][j4] = *(const float4*)&g_xc[r + hh * HEADDIM + pb + j4];
        }
        if (t < 32) {
            int idx = (b * SEQ + s0 + t) * NHEADS + hh;
            sdA[t] = g_dA[idx];
            sdt[t] = g_dt[idx];
        }
        __syncthreads();

        for (int si = 0; si < 32; si++) {
            float dAv = sdA[si];
            float xv  = sX[si][lp];
            float dtx = sdt[si] * xv;
            float4 b0 = *(const float4*)&sB[si][n0];
            float4 b1 = *(const float4*)&sB[si][n0 + 4];
            float4 c0 = *(const float4*)&sC[si][n0];
            float4 c1 = *(const float4*)&sC[si][n0 + 4];
            float yp;
            hst[0] = fmaf(hst[0], dAv, dtx * b0.x); yp  = hst[0] * c0.x;
            hst[1] = fmaf(hst[1], dAv, dtx * b0.y); yp += hst[1] * c0.y;
            hst[2] = fmaf(hst[2], dAv, dtx * b0.z); yp += hst[2] * c0.z;
            hst[3] = fmaf(hst[3], dAv, dtx * b0.w); yp += hst[3] * c0.w;
            hst[4] = fmaf(hst[4], dAv, dtx * b1.x); yp += hst[4] * c1.x;
            hst[5] = fmaf(hst[5], dAv, dtx * b1.y); yp += hst[5] * c1.y;
            hst[6] = fmaf(hst[6], dAv, dtx * b1.z); yp += hst[6] * c1.z;
            hst[7] = fmaf(hst[7], dAv, dtx * b1.w); yp += hst[7] * c1.w;
            yp += __shfl_xor_sync(0xffffffffu, yp, 1);
            yp += __shfl_xor_sync(0xffffffffu, yp, 2);
            yp += __shfl_xor_sync(0xffffffffu, yp, 4);
            if ((t & 7) == 0)
                g_y[(size_t)(b * SEQ + s0 + si) * DINNER + hh * HEADDIM + pb + lp] =
                    yp + Dh * xv;
        }
        __syncthreads();
    }

    size_t st = (((size_t)bz * NCHUNK + chunk) * HEADDIM + (pb + lp)) * DSTATE + n0;
    *(float4*)&g_state[st]     = make_float4(hst[0], hst[1], hst[2], hst[3]);
    *(float4*)&g_state[st + 4] = make_float4(hst[4], hst[5], hst[6], hst[7]);
}

// ---------------- pass 2: inter-chunk state scan ----------------
__global__ void __launch_bounds__(256)
state_scan_kernel()
{
    int idx = blockIdx.x * 256 + threadIdx.x;
    int n  = idx & 63;
    int p  = (idx >> 6) & 63;
    int bz = idx >> 12;
    int b  = bz >> 5, hh = bz & (NHEADS - 1);
    size_t base = (size_t)bz * (NCHUNK * HEADDIM * DSTATE) + (size_t)p * DSTATE + n;
    float hs = 0.0f;
#pragma unroll
    for (int c = 1; c < NCHUNK; c++) {
        float P = g_acum[((b * SEQ) + (c - 1) * CHUNK + (CHUNK - 1)) * NHEADS + hh];
        hs = fmaf(P, hs, g_state[base + (size_t)(c - 1) * (HEADDIM * DSTATE)]);
        g_hstart[base + (size_t)c * (HEADDIM * DSTATE)] = hs;
    }
}

// ---------------- pass 3: correction  y[t] += a(t) * (C[t] . h_start) ------
__global__ void __launch_bounds__(256)
scan_correction_kernel()
{
    const int c  = blockIdx.x + 1;        // chunks 1..7
    const int bz = blockIdx.y;
    const int b  = bz >> 5, hh = bz & (NHEADS - 1);
    const int tid = threadIdx.x;

    __shared__ __align__(16) float sHt[DSTATE][HEADDIM + 4];
    __shared__ __align__(16) float sC [CHUNK][DSTATE];
    __shared__ float sa[CHUNK];

    size_t hb = (size_t)bz * (NCHUNK * HEADDIM * DSTATE) + (size_t)c * (HEADDIM * DSTATE);
#pragma unroll
    for (int k = 0; k < 4; k++) {
        int i = tid + k * 256;
        int p = i >> 4, n4 = (i & 15) * 4;
        float4 v = *(const float4*)&g_hstart[hb + (size_t)p * DSTATE + n4];
        sHt[n4 + 0][p] = v.x; sHt[n4 + 1][p] = v.y;
        sHt[n4 + 2][p] = v.z; sHt[n4 + 3][p] = v.w;
    }
    const size_t rowbase = (size_t)(b * SEQ) * CONVDIM;
#pragma unroll
    for (int k = 0; k < 4; k++) {
        int i = tid + k * 256;
        int tt = i >> 4, n4 = (i & 15) * 4;
        *(float4*)&sC[tt][n4] =
            *(const float4*)&g_xc[rowbase + (size_t)(c * CHUNK + tt) * CONVDIM
                                  + DINNER + DSTATE + n4];
    }
    if (tid < CHUNK)
        sa[tid] = g_acum[(b * SEQ + c * CHUNK + tid) * NHEADS + hh];
    __syncthreads();

#pragma unroll
    for (int it = 0; it < 4; it++) {
        int o  = tid + it * 256;
        int tt = o >> 4, p4 = (o & 15) * 4;
        float4 acc = make_float4(0.f, 0.f, 0.f, 0.f);
#pragma unroll 8
        for (int n = 0; n < DSTATE; n++) {
            float  cv = sC[tt][n];
            float4 hv = *(const float4*)&sHt[n][p4];
            acc.x = fmaf(cv, hv.x, acc.x);
            acc.y = fmaf(cv, hv.y, acc.y);
            acc.z = fmaf(cv, hv.z, acc.z);
            acc.w = fmaf(cv, hv.w, acc.w);
        }
        float at = sa[tt];
        size_t yi = (size_t)(b * SEQ + c * CHUNK + tt) * DINNER + hh * HEADDIM + p4;
        float4 y = *(float4*)&g_y[yi];
        y.x = fmaf(at, acc.x, y.x);
        y.y = fmaf(at, acc.y, y.y);
        y.z = fmaf(at, acc.z, y.z);
        y.w = fmaf(at, acc.w, y.w);
        *(float4*)&g_y[yi] = y;
    }
}

// ---------------- gate + RMSNorm (writes tf32-rounded, K-PERMUTED) --------
__global__ void __launch_bounds__(256)
gate_norm_kernel(const float* __restrict__ norm_w)
{
    const int t = blockIdx.x;
    __shared__ float sg[DINNER];
    __shared__ float ssum[8];

    float local = 0.0f;
    for (int i = threadIdx.x; i < DINNER; i += 256) {
        float z = g_zx[(size_t)t * EPROJ + i];
        float g = g_y[(size_t)t * DINNER + i] * siluf(z);
        sg[i] = g;
        local = fmaf(g, g, local);
    }
#pragma unroll
    for (int off = 16; off; off >>= 1)
        local += __shfl_xor_sync(0xffffffffu, local, off);
    if ((threadIdx.x & 31) == 0) ssum[threadIdx.x >> 5] = local;
    __syncthreads();
    if (threadIdx.x < 8) {
        float v = ssum[threadIdx.x];
#pragma unroll
        for (int off = 4; off; off >>= 1)
            v += __shfl_xor_sync(0xffu, v, off);
        if (threadIdx.x == 0) ssum[0] = v;
    }
    __syncthreads();
    float scale = rsqrtf(ssum[0] / (float)DINNER + RMS_EPS);
    for (int i = threadIdx.x; i < DINNER; i += 256) {
        // permute within 8-group: l<4 -> 2l ; l>=4 -> 2(l-4)+1
        int p   = 2 * (i & 3) + ((i & 4) ? 1 : 0);
        int idx = (i & ~7) | p;
        g_nrm[(size_t)t * DINNER + idx] = tf32r(sg[i] * scale * norm_w[i]);
    }
}

// ---------------- merged decoders ----------------
__global__ void __launch_bounds__(128)
dec_kernel(const float* __restrict__ cw, const float* __restrict__ cb,
           const float* __restrict__ fw, const float* __restrict__ fb,
           float* __restrict__ out)
{
    int o = blockIdx.x * 4 + (threadIdx.x >> 5);
    int lane = threadIdx.x & 31;
    const float* hr;
    const float* wr;
    float bias;
    int oi;
    if (o < NTOK * VNUM) {
        int tok = o / VNUM, v = o % VNUM;
        hr = &g_h[(size_t)tok * DMODEL];
        wr = &cw[v * DMODEL];
        bias = cb[v];
        oi = o;
    } else {
        int o2 = o - NTOK * VNUM;
        if (o2 >= BATCH * HORIZON * VNUM) return;
        int b = o2 / (HORIZON * VNUM), j = o2 % (HORIZON * VNUM);
        hr = &g_h[(size_t)(b * SEQ + (SEQ - 1)) * DMODEL];
        wr = &fw[j * DMODEL];
        bias = fb[j];
        oi = NTOK * VNUM + o2;
    }
    float acc = 0.0f;
    for (int d = lane; d < DMODEL; d += 32) acc = fmaf(hr[d], wr[d], acc);
#pragma unroll
    for (int off = 16; off; off >>= 1)
        acc += __shfl_xor_sync(0xffffffffu, acc, off);
    if (lane == 0) out[oi] = acc + bias;
}

// ---------------- launch ----------------
extern "C" void kernel_launch(void* const* d_in, const int* in_sizes, int n_in,
                              void* d_out, int out_size)
{
    const float* embed      = (const float*)d_in[0];
    const float* in_proj_w  = (const float*)d_in[1];
    const float* conv_w     = (const float*)d_in[2];
    const float* conv_b     = (const float*)d_in[3];
    const float* dt_bias    = (const float*)d_in[4];
    const float* A_log      = (const float*)d_in[5];
    const float* Dp         = (const float*)d_in[6];
    const float* norm_w     = (const float*)d_in[7];
    const float* out_proj_w = (const float*)d_in[8];
    const float* dec_cur_w  = (const float*)d_in[9];
    const float* dec_cur_b  = (const float*)d_in[10];
    const float* dec_fut_w  = (const float*)d_in[11];
    const float* dec_fut_b  = (const float*)d_in[12];
    float* out = (float*)d_out;

    float *zx, *nrm, *h, *rA, *rW1, *rW2;
    cudaGetSymbolAddress((void**)&zx,  g_zx);
    cudaGetSymbolAddress((void**)&nrm, g_nrm);
    cudaGetSymbolAddress((void**)&h,   g_h);
    cudaGetSymbolAddress((void**)&rA,  g_rA);
    cudaGetSymbolAddress((void**)&rW1, g_rW1);
    cudaGetSymbolAddress((void**)&rW2, g_rW2);

    cudaFuncSetAttribute(gemm_tf32, cudaFuncAttributeMaxDynamicSharedMemorySize,
                         GEMM_SMEM_BYTES);

    // 0) round + K-permute all GEMM operands (one launch)
    {
        int total = N8_A + N8_W1 + N8_W2;
        round_perm_all<<<(total + 255) / 256, 256>>>(embed, in_proj_w, out_proj_w);
    }
    // 1) in_proj: [1024,1024] x [4256,1024]^T -> [1024,4256]
    {
        dim3 grid((EPROJ + TBN - 1) / TBN, NTOK / TBM);   // 67 x 8
        gemm_tf32<<<grid, 128, GEMM_SMEM_BYTES>>>(rA, rW1, zx, NTOK, EPROJ, DMODEL);
    }
    // 2) fused conv+silu and dt/la/dA
    conv_dt_kernel<<<(NTOK * (CONVDIM + NHEADS) + 255) / 256, 256>>>(conv_w, conv_b,
                                                                     dt_bias, A_log);
    // 3) within-chunk cumulative dA (warp log-scan)
    acum_kernel<<<64, 256>>>();
    // 4a) intra-chunk scan
    {
        dim3 grid(4, NCHUNK, BATCH * NHEADS);
        scan_chunk_kernel<<<grid, 128>>>(Dp);
    }
    // 4b) inter-chunk state scan
    state_scan_kernel<<<(BATCH * NHEADS * HEADDIM * DSTATE) / 256, 256>>>();
    // 4c) correction
    {
        dim3 grid(NCHUNK - 1, BATCH * NHEADS);
        scan_correction_kernel<<<grid, 256>>>();
    }
    // 5) gate + rmsnorm (tf32-rounded + permuted for out_proj)
    gate_norm_kernel<<<NTOK, 256>>>(norm_w);
    // 6) out_proj: [1024,2048] x [1024,2048]^T -> [1024,1024]
    {
        dim3 grid(DMODEL / TBN, NTOK / TBM);              // 16 x 8
        gemm_tf32<<<grid, 128, GEMM_SMEM_BYTES>>>(nrm, rW2, h, NTOK, DMODEL, DINNER);
    }
    // 7) merged decoders
    dec_kernel<<<(NTOK * VNUM + BATCH * HORIZON * VNUM + 3) / 4, 128>>>(
        dec_cur_w, dec_cur_b, dec_fut_w, dec_fut_b, out);
}

// round 17
// speedup vs baseline: 1.6489x; 1.0541x over previous
#include <cuda_runtime.h>
#include <math.h>
#include <stdint.h>

// ---------------- problem constants ----------------
#define BATCH   2
#define SEQ     512
#define NTOK    (BATCH*SEQ)          // 1024
#define DMODEL  1024
#define DINNER  2048
#define DSTATE  64
#define HEADDIM 64
#define NHEADS  32
#define CONVDIM (DINNER + 2*DSTATE)  // 2176
#define EPROJ   (2*DINNER + 2*DSTATE + NHEADS) // 4256
#define DCONV   4
#define VNUM    3
#define HORIZON 20
#define RMS_EPS 1e-5f
#define CHUNK   64
#define NCHUNK  (SEQ/CHUNK)          // 8
#define NSPLIT  2048                 // z columns (side-stream GEMM)
#define NREST   (EPROJ - NSPLIT)     // 2208 (critical-path GEMM)

// ---------------- device scratch (no cudaMalloc allowed) ----------------
__device__ float g_zx    [NTOK * EPROJ];    // in_proj output
__device__ float g_xc    [NTOK * CONVDIM];  // conv+silu output
__device__ float g_dt    [NTOK * NHEADS];   // softplus(dt)
__device__ float g_la    [NTOK * NHEADS];   // dt * A  (log of dA)
__device__ float g_dA    [NTOK * NHEADS];   // exp(dt*A)
__device__ float g_acum  [NTOK * NHEADS];   // within-chunk cumprod of dA
__device__ float g_state [BATCH*NHEADS*NCHUNK*HEADDIM*DSTATE]; // chunk-local end states
__device__ float g_hstart[BATCH*NHEADS*NCHUNK*HEADDIM*DSTATE]; // state at chunk start
__device__ float g_y     [NTOK * DINNER];   // scan output + D*x
__device__ float g_nrm   [NTOK * DINNER];   // gated+normed, tf32-rounded, K-PERMUTED
__device__ float g_h     [NTOK * DMODEL];   // out_proj output
// tf32-rounded + K-permuted GEMM operands ([k0,k4,k1,k5,k2,k6,k3,k7] per 8-group)
__device__ float g_rA    [NTOK * DMODEL];
__device__ float g_rW1   [EPROJ * DMODEL];
__device__ float g_rW2   [DMODEL * DINNER];

__device__ __forceinline__ float siluf(float x) { return x / (1.0f + expf(-x)); }
__device__ __forceinline__ float softplusf(float x) {
    return (x > 20.0f) ? x : log1pf(expf(x));
}
__device__ __forceinline__ float tf32r(float f) {
    uint32_t u;
    asm("cvt.rna.tf32.f32 %0, %1;\n" : "=r"(u) : "f"(f));
    return __uint_as_float(u);
}

// ---------------- cp.async helpers ----------------
__device__ __forceinline__ void cp_async16(void* smem, const void* gmem) {
    unsigned saddr = (unsigned)__cvta_generic_to_shared(smem);
    asm volatile("cp.async.cg.shared.global [%0], [%1], 16;\n" :: "r"(saddr), "l"(gmem));
}
__device__ __forceinline__ void cp_commit() {
    asm volatile("cp.async.commit_group;\n");
}
template <int N>
__device__ __forceinline__ void cp_wait() {
    asm volatile("cp.async.wait_group %0;\n" :: "n"(N));
}

// ---------------- tf32 round + K-permute (generic) ----------------
// Per 8-col k-group, output order [k0,k4,k1,k5,k2,k6,k3,k7].
#define N8_A  (NTOK * DMODEL / 8)      // 131072
#define N8_W1 (EPROJ * DMODEL / 8)     // 544768
#define N8_W2 (DMODEL * DINNER / 8)    // 262144

__global__ void __launch_bounds__(256)
round_perm_kernel(const float* __restrict__ in, float* __restrict__ out, int n8)
{
    int i = blockIdx.x * 256 + threadIdx.x;
    if (i >= n8) return;
    float4 v0 = *(const float4*)&in[i * 8];
    float4 v1 = *(const float4*)&in[i * 8 + 4];
    float4 o0 = make_float4(tf32r(v0.x), tf32r(v1.x), tf32r(v0.y), tf32r(v1.y));
    float4 o1 = make_float4(tf32r(v0.z), tf32r(v1.z), tf32r(v0.w), tf32r(v1.w));
    *(float4*)&out[i * 8]     = o0;
    *(float4*)&out[i * 8 + 4] = o1;
}

// ---------------- tf32 raw-mma GEMM NT (high-ILP warp tiles) --------------
// C[M, ldc-matrix], computes cols [0, Nlim) of this call's region.
// A row-major MxK; B row-major (region rows)xK; operands pre-rounded+permuted.
// BM=128, BN=64, BK=32; 128 threads = 4 warps (2m x 2n), warp tile 64x32.
#define TBM 128
#define TBN 64
#define TBK 32
#define TLD 40
#define STAGES 3
#define AS_STRIDE (TBM*TLD)              // 5120 floats / stage
#define BS_STRIDE (TBN*TLD)              // 2560 floats / stage
#define GEMM_SMEM_BYTES (STAGES*(AS_STRIDE+BS_STRIDE)*4)   // 92160 B

__device__ __forceinline__ void mma_tf32(float4& d,
                                         const uint32_t a0, const uint32_t a1,
                                         const uint32_t a2, const uint32_t a3,
                                         const uint32_t b0, const uint32_t b1) {
    asm volatile(
        "mma.sync.aligned.m16n8k8.row.col.f32.tf32.tf32.f32 "
        "{%0,%1,%2,%3}, {%4,%5,%6,%7}, {%8,%9}, {%0,%1,%2,%3};\n"
        : "+f"(d.x), "+f"(d.y), "+f"(d.z), "+f"(d.w)
        : "r"(a0), "r"(a1), "r"(a2), "r"(a3), "r"(b0), "r"(b1));
}

__global__ void __launch_bounds__(128)
gemm_tf32(const float* __restrict__ A, const float* __restrict__ B,
          float* __restrict__ C, int M, int ldc, int Nlim, int K)
{
    extern __shared__ __align__(16) float smem[];
    float* As = smem;                         // [STAGES][TBM][TLD]
    float* Bs = smem + STAGES * AS_STRIDE;    // [STAGES][TBN][TLD]

    const int tid  = threadIdx.x;
    const int lane = tid & 31;
    const int warp = tid >> 5;
    const int wm   = (warp & 1) * 64;    // 2 warps over M, tile 64
    const int wn   = (warp >> 1) * 32;   // 2 warps over N, tile 32
    const int m0   = blockIdx.y * TBM;
    const int n0   = blockIdx.x * TBN;

    float4 acc[4][4];
#pragma unroll
    for (int i = 0; i < 4; i++)
#pragma unroll
        for (int j = 0; j < 4; j++) acc[i][j] = make_float4(0.f, 0.f, 0.f, 0.f);

    const int ntiles = K / TBK;

    auto issue_tile = [&](int kt, int stg) {
        const size_t ko = (size_t)kt * TBK;
        float* as = As + stg * AS_STRIDE;
        float* bs = Bs + stg * BS_STRIDE;
#pragma unroll
        for (int k = 0; k < 8; k++) {            // 1024 float4 slots for A
            int slot = tid + k * 128;
            int r = slot >> 3, c = (slot & 7) * 4;
            cp_async16(&as[r * TLD + c], A + (size_t)(m0 + r) * K + ko + c);
        }
#pragma unroll
        for (int k = 0; k < 4; k++) {            // 512 float4 slots for B
            int slot = tid + k * 128;
            int r = slot >> 3, c = (slot & 7) * 4;
            int rr = (n0 + r < Nlim) ? (n0 + r) : (Nlim - 1); // clamp; masked at store
            cp_async16(&bs[r * TLD + c], B + (size_t)rr * K + ko + c);
        }
        cp_commit();
    };

    issue_tile(0, 0);
    if (ntiles > 1) issue_tile(1, 1);

    const int lr = lane >> 2;       // 0..7
    const int lc = lane & 3;        // 0..3

    for (int kt = 0; kt < ntiles; kt++) {
        if (kt + 1 == ntiles) cp_wait<0>(); else cp_wait<1>();
        __syncthreads();
        if (kt + STAGES - 1 < ntiles)
            issue_tile(kt + STAGES - 1, (kt + STAGES - 1) % STAGES);

        const float* Asw = As + (kt % STAGES) * AS_STRIDE + (size_t)(wm + lr) * TLD;
        const float* Bsw = Bs + (kt % STAGES) * BS_STRIDE + (size_t)(wn + lr) * TLD;

#pragma unroll
        for (int ks = 0; ks < TBK / 8; ks++) {
            const int kb = ks * 8 + 2 * lc;     // permuted: (lc, lc+4) adjacent
            uint32_t af[4][4];
#pragma unroll
            for (int i = 0; i < 4; i++) {
                const float* ap = Asw + i * 16 * TLD + kb;
                float2 u0 = *(const float2*)ap;              // rows lr / lr+8
                float2 u1 = *(const float2*)(ap + 8 * TLD);
                af[i][0] = __float_as_uint(u0.x);
                af[i][1] = __float_as_uint(u1.x);
                af[i][2] = __float_as_uint(u0.y);
                af[i][3] = __float_as_uint(u1.y);
            }
            uint32_t bf[4][2];
#pragma unroll
            for (int j = 0; j < 4; j++) {
                float2 v = *(const float2*)(Bsw + j * 8 * TLD + kb);
                bf[j][0] = __float_as_uint(v.x);
                bf[j][1] = __float_as_uint(v.y);
            }
#pragma unroll
            for (int i = 0; i < 4; i++)
#pragma unroll
                for (int j = 0; j < 4; j++)
                    mma_tf32(acc[i][j], af[i][0], af[i][1], af[i][2], af[i][3],
                             bf[j][0], bf[j][1]);
        }
    }

#pragma unroll
    for (int i = 0; i < 4; i++)
#pragma unroll
        for (int j = 0; j < 4; j++) {
            int r  = m0 + wm + i * 16 + lr;
            int cn = n0 + wn + j * 8 + lc * 2;
            if (cn < Nlim) {
                *(float2*)&C[(size_t)r * ldc + cn] =
                    make_float2(acc[i][j].x, acc[i][j].y);
                *(float2*)&C[(size_t)(r + 8) * ldc + cn] =
                    make_float2(acc[i][j].z, acc[i][j].w);
            }
        }
}

// ---------------- fused conv+silu and dt/la/dA ----------------
__global__ void __launch_bounds__(256)
conv_dt_kernel(const float* __restrict__ conv_w, const float* __restrict__ conv_b,
               const float* __restrict__ dt_bias, const float* __restrict__ A_log)
{
    int idx = blockIdx.x * blockDim.x + threadIdx.x;
    if (idx < NTOK * CONVDIM) {
        int c = idx % CONVDIM;
        int t = idx / CONVDIM;
        int s = t & (SEQ - 1);
        int b = t >> 9;
        float acc = conv_b[c];
#pragma unroll
        for (int k = 0; k < DCONV; k++) {
            int ss = s + k - (DCONV - 1);
            if (ss >= 0)
                acc = fmaf(conv_w[c * DCONV + k],
                           g_zx[(size_t)(b * SEQ + ss) * EPROJ + DINNER + c], acc);
        }
        g_xc[(size_t)t * CONVDIM + c] = siluf(acc);
    } else {
        int j = idx - NTOK * CONVDIM;
        if (j >= NTOK * NHEADS) return;
        int hh = j & (NHEADS - 1);
        int t  = j >> 5;
        float raw = g_zx[(size_t)t * EPROJ + DINNER + CONVDIM + hh];
        float dtv = softplusf(raw + dt_bias[hh]);
        float Ah  = -expf(A_log[hh]);
        float la  = dtv * Ah;
        g_dt[j] = dtv;
        g_la[j] = la;
        g_dA[j] = expf(la);
    }
}

// ---------------- within-chunk cumulative dA via warp log-scan ------------
__global__ void __launch_bounds__(256)
acum_kernel()
{
    int w    = (blockIdx.x * 256 + threadIdx.x) >> 5;   // 0..511
    int lane = threadIdx.x & 31;
    if (w >= BATCH * NHEADS * NCHUNK) return;
    int chunk = w & (NCHUNK - 1);
    int hh    = (w >> 3) & (NHEADS - 1);
    int b     = w >> 8;
    int base  = (b * SEQ + chunk * CHUNK) * NHEADS + hh;

    float l0 = g_la[base + (lane * 2)     * NHEADS];
    float l1 = g_la[base + (lane * 2 + 1) * NHEADS];
    float loc = l0 + l1;
    float sc = loc;
#pragma unroll
    for (int off = 1; off < 32; off <<= 1) {
        float v = __shfl_up_sync(0xffffffffu, sc, off);
        if (lane >= off) sc += v;
    }
    float excl = sc - loc;
    g_acum[base + (lane * 2)     * NHEADS] = expf(excl + l0);
    g_acum[base + (lane * 2 + 1) * NHEADS] = expf(excl + loc);
}

// ---------------- pass 1: intra-chunk scan (zero initial state) ----------------
__global__ void __launch_bounds__(128)
scan_chunk_kernel(const float* __restrict__ Dp)
{
    const int bz = blockIdx.z;
    const int b  = bz >> 5;
    const int hh = bz & (NHEADS - 1);
    const int chunk = blockIdx.y;
    const int pb = blockIdx.x * 16;
    const int t  = threadIdx.x;
    const int lp = t >> 3;
    const int n0 = (t & 7) * 8;

    __shared__ __align__(16) float sB[32][64];
    __shared__ __align__(16) float sC[32][64];
    __shared__ __align__(16) float sX[32][16];
    __shared__ float sdA[32], sdt[32];

    float hst[8];
#pragma unroll
    for (int j = 0; j < 8; j++) hst[j] = 0.0f;

    const float Dh = Dp[hh];
    const size_t rowbase = (size_t)(b * SEQ) * CONVDIM;

#pragma unroll
    for (int sub = 0; sub < 2; sub++) {
        const int s0 = chunk * CHUNK + sub * 32;
        for (int i = t; i < 512; i += 128) {
            int si = i >> 4, j4 = (i & 15) * 4;
            size_t r = rowbase + (size_t)(s0 + si) * CONVDIM;
            *(float4*)&sB[si][j4] = *(const float4*)&g_xc[r + DINNER + j4];
            *(float4*)&sC[si][j4] = *(const float4*)&g_xc[r + DINNER + DSTATE + j4];
        }
        {
            int si = t >> 2, j4 = (t & 3) * 4;
            size_t r = rowbase + (size_t)(s0 + si) * CONVDIM;
            *(float4*)&sX[si][j4] = *(const float4*)&g_xc[r + hh * HEADDIM + pb + j4];
        }
        if (t < 32) {
            int idx = (b * SEQ + s0 + t) * NHEADS + hh;
            sdA[t] = g_dA[idx];
            sdt[t] = g_dt[idx];
        }
        __syncthreads();

        for (int si = 0; si < 32; si++) {
            float dAv = sdA[si];
            float xv  = sX[si][lp];
            float dtx = sdt[si] * xv;
            float4 b0 = *(const float4*)&sB[si][n0];
            float4 b1 = *(const float4*)&sB[si][n0 + 4];
            float4 c0 = *(const float4*)&sC[si][n0];
            float4 c1 = *(const float4*)&sC[si][n0 + 4];
            float yp;
            hst[0] = fmaf(hst[0], dAv, dtx * b0.x); yp  = hst[0] * c0.x;
            hst[1] = fmaf(hst[1], dAv, dtx * b0.y); yp += hst[1] * c0.y;
            hst[2] = fmaf(hst[2], dAv, dtx * b0.z); yp += hst[2] * c0.z;
            hst[3] = fmaf(hst[3], dAv, dtx * b0.w); yp += hst[3] * c0.w;
            hst[4] = fmaf(hst[4], dAv, dtx * b1.x); yp += hst[4] * c1.x;
            hst[5] = fmaf(hst[5], dAv, dtx * b1.y); yp += hst[5] * c1.y;
            hst[6] = fmaf(hst[6], dAv, dtx * b1.z); yp += hst[6] * c1.z;
            hst[7] = fmaf(hst[7], dAv, dtx * b1.w); yp += hst[7] * c1.w;
            yp += __shfl_xor_sync(0xffffffffu, yp, 1);
            yp += __shfl_xor_sync(0xffffffffu, yp, 2);
            yp += __shfl_xor_sync(0xffffffffu, yp, 4);
            if ((t & 7) == 0)
                g_y[(size_t)(b * SEQ + s0 + si) * DINNER + hh * HEADDIM + pb + lp] =
                    yp + Dh * xv;
        }
        __syncthreads();
    }

    size_t st = (((size_t)bz * NCHUNK + chunk) * HEADDIM + (pb + lp)) * DSTATE + n0;
    *(float4*)&g_state[st]     = make_float4(hst[0], hst[1], hst[2], hst[3]);
    *(float4*)&g_state[st + 4] = make_float4(hst[4], hst[5], hst[6], hst[7]);
}

// ---------------- pass 2: inter-chunk state scan ----------------
__global__ void __launch_bounds__(256)
state_scan_kernel()
{
    int idx = blockIdx.x * 256 + threadIdx.x;
    int n  = idx & 63;
    int p  = (idx >> 6) & 63;
    int bz = idx >> 12;
    int b  = bz >> 5, hh = bz & (NHEADS - 1);
    size_t base = (size_t)bz * (NCHUNK * HEADDIM * DSTATE) + (size_t)p * DSTATE + n;
    float hs = 0.0f;
#pragma unroll
    for (int c = 1; c < NCHUNK; c++) {
        float P = g_acum[((b * SEQ) + (c - 1) * CHUNK + (CHUNK - 1)) * NHEADS + hh];
        hs = fmaf(P, hs, g_state[base + (size_t)(c - 1) * (HEADDIM * DSTATE)]);
        g_hstart[base + (size_t)c * (HEADDIM * DSTATE)] = hs;
    }
}

// ---------------- pass 3: correction  y[t] += a(t) * (C[t] . h_start) ------
__global__ void __launch_bounds__(256)
scan_correction_kernel()
{
    const int c  = blockIdx.x + 1;        // chunks 1..7
    const int bz = blockIdx.y;
    const int b  = bz >> 5, hh = bz & (NHEADS - 1);
    const int tid = threadIdx.x;

    __shared__ __align__(16) float sHt[DSTATE][HEADDIM + 4];
    __shared__ __align__(16) float sC [CHUNK][DSTATE];
    __shared__ float sa[CHUNK];

    size_t hb = (size_t)bz * (NCHUNK * HEADDIM * DSTATE) + (size_t)c * (HEADDIM * DSTATE);
#pragma unroll
    for (int k = 0; k < 4; k++) {
        int i = tid + k * 256;
        int p = i >> 4, n4 = (i & 15) * 4;
        float4 v = *(const float4*)&g_hstart[hb + (size_t)p * DSTATE + n4];
        sHt[n4 + 0][p] = v.x; sHt[n4 + 1][p] = v.y;
        sHt[n4 + 2][p] = v.z; sHt[n4 + 3][p] = v.w;
    }
    const size_t rowbase = (size_t)(b * SEQ) * CONVDIM;
#pragma unroll
    for (int k = 0; k < 4; k++) {
        int i = tid + k * 256;
        int tt = i >> 4, n4 = (i & 15) * 4;
        *(float4*)&sC[tt][n4] =
            *(const float4*)&g_xc[rowbase + (size_t)(c * CHUNK + tt) * CONVDIM
                                  + DINNER + DSTATE + n4];
    }
    if (tid < CHUNK)
        sa[tid] = g_acum[(b * SEQ + c * CHUNK + tid) * NHEADS + hh];
    __syncthreads();

#pragma unroll
    for (int it = 0; it < 4; it++) {
        int o  = tid + it * 256;
        int tt = o >> 4, p4 = (o & 15) * 4;
        float4 acc = make_float4(0.f, 0.f, 0.f, 0.f);
#pragma unroll 8
        for (int n = 0; n < DSTATE; n++) {
            float  cv = sC[tt][n];
            float4 hv = *(const float4*)&sHt[n][p4];
            acc.x = fmaf(cv, hv.x, acc.x);
            acc.y = fmaf(cv, hv.y, acc.y);
            acc.z = fmaf(cv, hv.z, acc.z);
            acc.w = fmaf(cv, hv.w, acc.w);
        }
        float at = sa[tt];
        size_t yi = (size_t)(b * SEQ + c * CHUNK + tt) * DINNER + hh * HEADDIM + p4;
        float4 y = *(float4*)&g_y[yi];
        y.x = fmaf(at, acc.x, y.x);
        y.y = fmaf(at, acc.y, y.y);
        y.z = fmaf(at, acc.z, y.z);
        y.w = fmaf(at, acc.w, y.w);
        *(float4*)&g_y[yi] = y;
    }
}

// ---------------- gate + RMSNorm (writes tf32-rounded, K-PERMUTED) --------
__global__ void __launch_bounds__(256)
gate_norm_kernel(const float* __restrict__ norm_w)
{
    const int t = blockIdx.x;
    __shared__ float sg[DINNER];
    __shared__ float ssum[8];

    float local = 0.0f;
    for (int i = threadIdx.x; i < DINNER; i += 256) {
        float z = g_zx[(size_t)t * EPROJ + i];
        float g = g_y[(size_t)t * DINNER + i] * siluf(z);
        sg[i] = g;
        local = fmaf(g, g, local);
    }
#pragma unroll
    for (int off = 16; off; off >>= 1)
        local += __shfl_xor_sync(0xffffffffu, local, off);
    if ((threadIdx.x & 31) == 0) ssum[threadIdx.x >> 5] = local;
    __syncthreads();
    if (threadIdx.x < 8) {
        float v = ssum[threadIdx.x];
#pragma unroll
        for (int off = 4; off; off >>= 1)
            v += __shfl_xor_sync(0xffu, v, off);
        if (threadIdx.x == 0) ssum[0] = v;
    }
    __syncthreads();
    float scale = rsqrtf(ssum[0] / (float)DINNER + RMS_EPS);
    for (int i = threadIdx.x; i < DINNER; i += 256) {
        // permute within 8-group: l<4 -> 2l ; l>=4 -> 2(l-4)+1
        int p   = 2 * (i & 3) + ((i & 4) ? 1 : 0);
        int idx = (i & ~7) | p;
        g_nrm[(size_t)t * DINNER + idx] = tf32r(sg[i] * scale * norm_w[i]);
    }
}

// ---------------- merged decoders ----------------
__global__ void __launch_bounds__(128)
dec_kernel(const float* __restrict__ cw, const float* __restrict__ cb,
           const float* __restrict__ fw, const float* __restrict__ fb,
           float* __restrict__ out)
{
    int o = blockIdx.x * 4 + (threadIdx.x >> 5);
    int lane = threadIdx.x & 31;
    const float* hr;
    const float* wr;
    float bias;
    int oi;
    if (o < NTOK * VNUM) {
        int tok = o / VNUM, v = o % VNUM;
        hr = &g_h[(size_t)tok * DMODEL];
        wr = &cw[v * DMODEL];
        bias = cb[v];
        oi = o;
    } else {
        int o2 = o - NTOK * VNUM;
        if (o2 >= BATCH * HORIZON * VNUM) return;
        int b = o2 / (HORIZON * VNUM), j = o2 % (HORIZON * VNUM);
        hr = &g_h[(size_t)(b * SEQ + (SEQ - 1)) * DMODEL];
        wr = &fw[j * DMODEL];
        bias = fb[j];
        oi = NTOK * VNUM + o2;
    }
    float acc = 0.0f;
    for (int d = lane; d < DMODEL; d += 32) acc = fmaf(hr[d], wr[d], acc);
#pragma unroll
    for (int off = 16; off; off >>= 1)
        acc += __shfl_xor_sync(0xffffffffu, acc, off);
    if (lane == 0) out[oi] = acc + bias;
}

// ---------------- launch ----------------
extern "C" void kernel_launch(void* const* d_in, const int* in_sizes, int n_in,
                              void* d_out, int out_size)
{
    const float* embed      = (const float*)d_in[0];
    const float* in_proj_w  = (const float*)d_in[1];
    const float* conv_w     = (const float*)d_in[2];
    const float* conv_b     = (const float*)d_in[3];
    const float* dt_bias    = (const float*)d_in[4];
    const float* A_log      = (const float*)d_in[5];
    const float* Dp         = (const float*)d_in[6];
    const float* norm_w     = (const float*)d_in[7];
    const float* out_proj_w = (const float*)d_in[8];
    const float* dec_cur_w  = (const float*)d_in[9];
    const float* dec_cur_b  = (const float*)d_in[10];
    const float* dec_fut_w  = (const float*)d_in[11];
    const float* dec_fut_b  = (const float*)d_in[12];
    float* out = (float*)d_out;

    float *zx, *nrm, *h, *rA, *rW1, *rW2;
    cudaGetSymbolAddress((void**)&zx,  g_zx);
    cudaGetSymbolAddress((void**)&nrm, g_nrm);
    cudaGetSymbolAddress((void**)&h,   g_h);
    cudaGetSymbolAddress((void**)&rA,  g_rA);
    cudaGetSymbolAddress((void**)&rW1, g_rW1);
    cudaGetSymbolAddress((void**)&rW2, g_rW2);

    cudaFuncSetAttribute(gemm_tf32, cudaFuncAttributeMaxDynamicSharedMemorySize,
                         GEMM_SMEM_BYTES);

    // side stream + events for overlap (host objects only; leaked by design —
    // kernel_launch runs twice: correctness + capture; no device allocations)
    cudaStream_t s1;
    cudaStreamCreateWithFlags(&s1, cudaStreamNonBlocking);
    cudaEvent_t evStart, ev1, ev2;
    cudaEventCreateWithFlags(&evStart, cudaEventDisableTiming);
    cudaEventCreateWithFlags(&ev1,     cudaEventDisableTiming);
    cudaEventCreateWithFlags(&ev2,     cudaEventDisableTiming);

    // fork side stream from capture origin
    cudaEventRecord(evStart, 0);
    cudaStreamWaitEvent(s1, evStart, 0);

    // side: round W2 (needed only by out_proj, late)
    round_perm_kernel<<<(N8_W2 + 255) / 256, 256, 0, s1>>>(out_proj_w, rW2, N8_W2);

    // main: round A and W1 (needed by both in_proj halves)
    round_perm_kernel<<<(N8_A  + 255) / 256, 256>>>(embed,     rA,  N8_A);
    round_perm_kernel<<<(N8_W1 + 255) / 256, 256>>>(in_proj_w, rW1, N8_W1);
    cudaEventRecord(ev1, 0);

    // side: in_proj_A = z columns [0, 2048) — only needed at gate_norm
    cudaStreamWaitEvent(s1, ev1, 0);
    {
        dim3 grid(NSPLIT / TBN, NTOK / TBM);              // 32 x 8
        gemm_tf32<<<grid, 128, GEMM_SMEM_BYTES, s1>>>(rA, rW1, zx,
                                                      NTOK, EPROJ, NSPLIT, DMODEL);
    }
    cudaEventRecord(ev2, s1);

    // main (critical path): in_proj_B = xBC+dt columns [2048, 4256)
    {
        dim3 grid((NREST + TBN - 1) / TBN, NTOK / TBM);   // 35 x 8
        gemm_tf32<<<grid, 128, GEMM_SMEM_BYTES>>>(rA, rW1 + (size_t)NSPLIT * DMODEL,
                                                  zx + NSPLIT,
                                                  NTOK, EPROJ, NREST, DMODEL);
    }
    // conv+silu and dt/la/dA (reads zx cols >= 2048 only)
    conv_dt_kernel<<<(NTOK * (CONVDIM + NHEADS) + 255) / 256, 256>>>(conv_w, conv_b,
                                                                     dt_bias, A_log);
    acum_kernel<<<64, 256>>>();
    {
        dim3 grid(4, NCHUNK, BATCH * NHEADS);
        scan_chunk_kernel<<<grid, 128>>>(Dp);
    }
    state_scan_kernel<<<(BATCH * NHEADS * HEADDIM * DSTATE) / 256, 256>>>();
    {
        dim3 grid(NCHUNK - 1, BATCH * NHEADS);
        scan_correction_kernel<<<grid, 256>>>();
    }

    // join side stream: gate_norm reads z columns from in_proj_A
    cudaStreamWaitEvent(0, ev2, 0);
    gate_norm_kernel<<<NTOK, 256>>>(norm_w);
    {
        dim3 grid(DMODEL / TBN, NTOK / TBM);              // 16 x 8
        gemm_tf32<<<grid, 128, GEMM_SMEM_BYTES>>>(nrm, rW2, h,
                                                  NTOK, DMODEL, DMODEL, DINNER);
    }
    dec_kernel<<<(NTOK * VNUM + BATCH * HORIZON * VNUM + 3) / 4, 128>>>(
        dec_cur_w, dec_cur_b, dec_fut_w, dec_fut_b, out);
}